// round 1
// baseline (speedup 1.0000x reference)
#include <cuda_runtime.h>
#include <math.h>

#define DIM   1024
#define NH    16
#define NKV   4
#define HD    64
#define WIN   512
#define BB    2
#define SS    2048
#define TT    (BB*SS)
#define QKVW  1536   // 1024 q | 256 k | 256 v per token

// ---------------- scratch (no allocs allowed) ----------------
__device__ float g_xqkv[(size_t)TT * QKVW];  // 25 MB
__device__ float g_attn[(size_t)TT * DIM];   // 16 MB

// ---------------- GEMM: C[m, coff+n] = sum_k A[m,k] * W[n,k] ----------------
#define BM 128
#define BN 128
#define BKK 16
#define SPAD 4   // smem row stride 132 floats: keeps 16B alignment, kills most STS conflicts

__global__ __launch_bounds__(256) void sgemm_nt(
    const float* __restrict__ A,   // [M, K] row-major
    const float* __restrict__ W,   // [N, K] row-major
    float* __restrict__ C,         // rows of length ldc, write at col offset coff
    int M, int N, int K, int ldc, int coff)
{
    __shared__ float As[BKK][BM + SPAD];
    __shared__ float Ws[BKK][BN + SPAD];

    const int tid = threadIdx.x;
    const int m0 = blockIdx.y * BM;
    const int n0 = blockIdx.x * BN;

    // tile-load mapping: 2 float4 per thread for A and for W
    const int lr = tid >> 2;            // 0..63
    const int lk = (tid & 3) << 2;      // 0,4,8,12
    const int ty = tid >> 4;            // 0..15
    const int tx = tid & 15;            // 0..15

    float acc[8][8];
#pragma unroll
    for (int i = 0; i < 8; i++)
#pragma unroll
        for (int j = 0; j < 8; j++) acc[i][j] = 0.f;

    const float* Ap = A + (size_t)(m0 + lr) * K + lk;
    const float* Wp = W + (size_t)(n0 + lr) * K + lk;

    for (int k0 = 0; k0 < K; k0 += BKK) {
#pragma unroll
        for (int h = 0; h < 2; h++) {
            int row = lr + h * 64;
            float4 a = *(const float4*)(Ap + (size_t)h * 64 * K + k0);
            As[lk + 0][row] = a.x; As[lk + 1][row] = a.y;
            As[lk + 2][row] = a.z; As[lk + 3][row] = a.w;
            float4 w = *(const float4*)(Wp + (size_t)h * 64 * K + k0);
            Ws[lk + 0][row] = w.x; Ws[lk + 1][row] = w.y;
            Ws[lk + 2][row] = w.z; Ws[lk + 3][row] = w.w;
        }
        __syncthreads();

#pragma unroll
        for (int kk = 0; kk < BKK; kk++) {
            float a[8], b[8];
            *(float4*)&a[0] = *(const float4*)&As[kk][ty * 8];
            *(float4*)&a[4] = *(const float4*)&As[kk][ty * 8 + 4];
            *(float4*)&b[0] = *(const float4*)&Ws[kk][tx * 8];
            *(float4*)&b[4] = *(const float4*)&Ws[kk][tx * 8 + 4];
#pragma unroll
            for (int i = 0; i < 8; i++)
#pragma unroll
                for (int j = 0; j < 8; j++)
                    acc[i][j] = fmaf(a[i], b[j], acc[i][j]);
        }
        __syncthreads();
    }

#pragma unroll
    for (int i = 0; i < 8; i++) {
        float* crow = C + (size_t)(m0 + ty * 8 + i) * ldc + coff + n0 + tx * 8;
        float4 r0 = make_float4(acc[i][0], acc[i][1], acc[i][2], acc[i][3]);
        float4 r1 = make_float4(acc[i][4], acc[i][5], acc[i][6], acc[i][7]);
        *(float4*)crow = r0;
        *(float4*)(crow + 4) = r1;
    }
}

// ---------------- RMSNorm over q part (1024 wide) ----------------
__global__ __launch_bounds__(256) void rms_q(const float* __restrict__ w)
{
    const int t = blockIdx.x;
    float* row = g_xqkv + (size_t)t * QKVW;
    const int tid = threadIdx.x;

    float v[4];
    float ss = 0.f;
#pragma unroll
    for (int i = 0; i < 4; i++) {
        v[i] = row[tid + 256 * i];
        ss = fmaf(v[i], v[i], ss);
    }
#pragma unroll
    for (int o = 16; o > 0; o >>= 1) ss += __shfl_xor_sync(0xffffffffu, ss, o);

    __shared__ float red[8];
    __shared__ float sscl;
    if ((tid & 31) == 0) red[tid >> 5] = ss;
    __syncthreads();
    if (tid == 0) {
        float tot = 0.f;
#pragma unroll
        for (int i = 0; i < 8; i++) tot += red[i];
        sscl = rsqrtf(tot * (1.f / 1024.f) + 1e-6f);
    }
    __syncthreads();
    float scl = sscl;
#pragma unroll
    for (int i = 0; i < 4; i++) {
        int idx = tid + 256 * i;
        row[idx] = v[i] * scl * w[idx];
    }
}

// ---------------- RMSNorm over k part (256 wide, at offset 1024) ----------------
__global__ __launch_bounds__(256) void rms_k(const float* __restrict__ w)
{
    const int t = blockIdx.x;
    float* row = g_xqkv + (size_t)t * QKVW + 1024;
    const int tid = threadIdx.x;

    float v = row[tid];
    float ss = v * v;
#pragma unroll
    for (int o = 16; o > 0; o >>= 1) ss += __shfl_xor_sync(0xffffffffu, ss, o);

    __shared__ float red[8];
    __shared__ float sscl;
    if ((tid & 31) == 0) red[tid >> 5] = ss;
    __syncthreads();
    if (tid == 0) {
        float tot = 0.f;
#pragma unroll
        for (int i = 0; i < 8; i++) tot += red[i];
        sscl = rsqrtf(tot * (1.f / 256.f) + 1e-6f);
    }
    __syncthreads();
    row[tid] = v * sscl * w[tid];
}

// ---------------- Attention ----------------
// grid: (S/64, NKV, B); block 256. thread = (gqa head 0..3) x (query 0..63).
__global__ __launch_bounds__(256) void attn_kernel()
{
    __shared__ float Ks[16][HD];
    __shared__ float Vs[16][HD];

    const int tid = threadIdx.x;
    const int qi = tid & 63;
    const int hl = tid >> 6;                 // 0..3
    const int kvh = blockIdx.y;
    const int b = blockIdx.z;
    const int head = kvh * 4 + hl;
    const int qstart = blockIdx.x * 64;
    const int qpos = qstart + qi;

    const float scale = 0.125f;              // 1/sqrt(64)
    const float slope = exp2f(-0.5f * (float)(head + 1));   // 2^(-8(h+1)/16)

    float q[HD];
    {
        const float* qp = g_xqkv + (size_t)(b * SS + qpos) * QKVW + head * HD;
#pragma unroll
        for (int d = 0; d < HD; d += 4) {
            float4 v = *(const float4*)(qp + d);
            q[d] = v.x * scale; q[d + 1] = v.y * scale;
            q[d + 2] = v.z * scale; q[d + 3] = v.w * scale;
        }
    }

    float o[HD];
#pragma unroll
    for (int d = 0; d < HD; d++) o[d] = 0.f;
    float m = -INFINITY, l = 0.f;

    int kstart = qstart - WIN; if (kstart < 0) kstart = 0;
    const int kend = qstart + 64;

    const int lrow = tid >> 4;               // 0..15
    const int lcol = (tid & 15) << 2;        // 0..60

    for (int kc = kstart; kc < kend; kc += 16) {
        {
            const float* base = g_xqkv + (size_t)(b * SS + kc + lrow) * QKVW;
            *(float4*)&Ks[lrow][lcol] = *(const float4*)(base + 1024 + kvh * HD + lcol);
            *(float4*)&Vs[lrow][lcol] = *(const float4*)(base + 1280 + kvh * HD + lcol);
        }
        __syncthreads();

        float s[16];
#pragma unroll
        for (int j = 0; j < 16; j++) {
            float acc = 0.f;
#pragma unroll
            for (int d = 0; d < HD; d += 4) {
                float4 kv = *(const float4*)&Ks[j][d];
                acc = fmaf(q[d],     kv.x, acc);
                acc = fmaf(q[d + 1], kv.y, acc);
                acc = fmaf(q[d + 2], kv.z, acc);
                acc = fmaf(q[d + 3], kv.w, acc);
            }
            int kpos = kc + j;
            bool ok = (kpos <= qpos) && (kpos + WIN >= qpos);
            s[j] = ok ? fmaf(slope, (float)(kpos - qpos), acc) : -INFINITY;
        }

        float cmax = s[0];
#pragma unroll
        for (int j = 1; j < 16; j++) cmax = fmaxf(cmax, s[j]);
        float m_new = fmaxf(m, cmax);

        if (m_new > -INFINITY) {
            float alpha = __expf(m - m_new);   // m=-inf -> 0
            l *= alpha;
#pragma unroll
            for (int d = 0; d < HD; d++) o[d] *= alpha;
#pragma unroll
            for (int j = 0; j < 16; j++) {
                float p = __expf(s[j] - m_new);  // masked -> 0
                l += p;
#pragma unroll
                for (int d = 0; d < HD; d += 4) {
                    float4 vv = *(const float4*)&Vs[j][d];
                    o[d]     = fmaf(p, vv.x, o[d]);
                    o[d + 1] = fmaf(p, vv.y, o[d + 1]);
                    o[d + 2] = fmaf(p, vv.z, o[d + 2]);
                    o[d + 3] = fmaf(p, vv.w, o[d + 3]);
                }
            }
            m = m_new;
        }
        __syncthreads();
    }

    float inv = 1.f / l;
    float* op = g_attn + (size_t)(b * SS + qpos) * DIM + head * HD;
#pragma unroll
    for (int d = 0; d < HD; d += 4) {
        float4 r = make_float4(o[d] * inv, o[d + 1] * inv, o[d + 2] * inv, o[d + 3] * inv);
        *(float4*)(op + d) = r;
    }
}

// ---------------- launch ----------------
extern "C" void kernel_launch(void* const* d_in, const int* in_sizes, int n_in,
                              void* d_out, int out_size)
{
    const float* x  = (const float*)d_in[0];
    const float* wq = (const float*)d_in[1];
    const float* wk = (const float*)d_in[2];
    const float* wv = (const float*)d_in[3];
    const float* wo = (const float*)d_in[4];
    const float* qw = (const float*)d_in[5];
    const float* kw = (const float*)d_in[6];
    float* out = (float*)d_out;

    float* xqkv = nullptr;
    float* attn = nullptr;
    cudaGetSymbolAddress((void**)&xqkv, g_xqkv);
    cudaGetSymbolAddress((void**)&attn, g_attn);

    // QKV projections into one [T, 1536] buffer
    sgemm_nt<<<dim3(DIM / BN, TT / BM), 256>>>(x, wq, xqkv, TT, DIM, DIM, QKVW, 0);
    sgemm_nt<<<dim3(256 / BN, TT / BM), 256>>>(x, wk, xqkv, TT, 256, DIM, QKVW, 1024);
    sgemm_nt<<<dim3(256 / BN, TT / BM), 256>>>(x, wv, xqkv, TT, 256, DIM, QKVW, 1280);

    rms_q<<<TT, 256>>>(qw);
    rms_k<<<TT, 256>>>(kw);

    attn_kernel<<<dim3(SS / 64, NKV, BB), 256>>>();

    // output projection
    sgemm_nt<<<dim3(DIM / BN, TT / BM), 256>>>(attn, wo, out, TT, DIM, DIM, DIM, 0);
}

// round 3
// speedup vs baseline: 1.4366x; 1.4366x over previous
#include <cuda_runtime.h>
#include <cuda_bf16.h>
#include <math.h>
#include <stdint.h>

#define DIM   1024
#define NH    16
#define NKV   4
#define HD    64
#define WIN   512
#define BB    2
#define SS    2048
#define TT    (BB*SS)
#define QKVW  1536   // 1024 q | 256 k | 256 v per token
#define GK    1024   // K dim of every GEMM

// ---------------- scratch (no allocs allowed) ----------------
__device__ float g_xqkv[(size_t)TT * QKVW];          // 25 MB fp32 qkv
__device__ float g_attn[(size_t)TT * DIM];           // 16 MB fp32 attn out
__device__ __nv_bfloat16 g_ah[(size_t)TT * DIM];     // activation hi (x, then attn)
__device__ __nv_bfloat16 g_al[(size_t)TT * DIM];     // activation lo
__device__ __nv_bfloat16 g_wh[(size_t)2560 * DIM];   // weights hi: wq|wk|wv|wo (stacked rows)
__device__ __nv_bfloat16 g_wl[(size_t)2560 * DIM];   // weights lo
#define WQ_ROW 0
#define WK_ROW 1024
#define WV_ROW 1280
#define WO_ROW 1536

// ---------------- fp32 -> bf16 hi/lo split ----------------
__global__ __launch_bounds__(256) void split_bf16(
    const float* __restrict__ in, __nv_bfloat16* __restrict__ hi,
    __nv_bfloat16* __restrict__ lo, int n4)
{
    int i = blockIdx.x * 256 + threadIdx.x;
    if (i >= n4) return;
    float4 v = ((const float4*)in)[i];
    float f[4] = {v.x, v.y, v.z, v.w};
    union { __nv_bfloat16 b[4]; uint2 u; } H, L;
#pragma unroll
    for (int k = 0; k < 4; k++) {
        __nv_bfloat16 h = __float2bfloat16(f[k]);
        H.b[k] = h;
        L.b[k] = __float2bfloat16(f[k] - __bfloat162float(h));
    }
    ((uint2*)hi)[i] = H.u;
    ((uint2*)lo)[i] = L.u;
}

// ---------------- HMMA split-bf16 GEMM ----------------
// C[m0+i, coff+n0+j] = sum_k A[i,k]*B[j,k]  (both K-major, hi/lo bf16)
// block 256 = 8 warps (2 m x 4 n), warp tile 64x32, BK=32, double-buffered smem.
// smem tiles: [128 rows][40 halves] (80B stride -> conflict-free quad LDS)
#define SROW 40
#define TILE_H (128 * SROW)                 // halves per tile
#define STAGE_H (4 * TILE_H)                // Ah, Al, Bh, Bl
#define GEMM_SMEM (2 * STAGE_H * 2)         // bytes

#define MMA_BF16(c0,c1,c2,c3, a0,a1,a2,a3, b0,b1) \
    asm volatile("mma.sync.aligned.m16n8k16.row.col.f32.bf16.bf16.f32 " \
                 "{%0,%1,%2,%3}, {%4,%5,%6,%7}, {%8,%9}, {%0,%1,%2,%3};" \
                 : "+f"(c0), "+f"(c1), "+f"(c2), "+f"(c3) \
                 : "r"(a0), "r"(a1), "r"(a2), "r"(a3), "r"(b0), "r"(b1))

__global__ __launch_bounds__(256) void hmma_gemm(
    const __nv_bfloat16* __restrict__ ah, const __nv_bfloat16* __restrict__ al,
    const __nv_bfloat16* __restrict__ bh, const __nv_bfloat16* __restrict__ bl,
    float* __restrict__ C, int ldc, int coff)
{
    extern __shared__ __nv_bfloat16 smem[];

    const int tid = threadIdx.x;
    const int wid = tid >> 5;
    const int lid = tid & 31;
    const int wm = wid & 1;          // 0..1
    const int wn = wid >> 1;         // 0..3
    const int m0 = blockIdx.y * 128;
    const int n0 = blockIdx.x * 128;

    // global load mapping: thread -> (row = tid>>1, 16-half chunk = tid&1)
    const int grow = tid >> 1;
    const int gcp = (tid & 1) * 16;  // half offset within row

    const __nv_bfloat16* gsrc[4];
    gsrc[0] = ah + (size_t)(m0 + grow) * GK + gcp;
    gsrc[1] = al + (size_t)(m0 + grow) * GK + gcp;
    gsrc[2] = bh + (size_t)(n0 + grow) * GK + gcp;
    gsrc[3] = bl + (size_t)(n0 + grow) * GK + gcp;
    const int soff = grow * SROW + gcp;

    float acc[4][4][4];
#pragma unroll
    for (int i = 0; i < 4; i++)
#pragma unroll
        for (int j = 0; j < 4; j++)
#pragma unroll
            for (int k = 0; k < 4; k++) acc[i][j][k] = 0.f;

    const int r2 = lid >> 2;         // 0..7
    const int c2 = (lid & 3) * 2;    // 0,2,4,6

    // prologue: stage 0
#pragma unroll
    for (int t = 0; t < 4; t++) {
        uint4 v0 = *(const uint4*)(gsrc[t]);
        uint4 v1 = *(const uint4*)(gsrc[t] + 8);
        *(uint4*)(smem + t * TILE_H + soff) = v0;
        *(uint4*)(smem + t * TILE_H + soff + 8) = v1;
    }
    __syncthreads();

    for (int kc = 0; kc < GK / 32; kc++) {
        const int cur = kc & 1;
        const __nv_bfloat16* sb = smem + cur * STAGE_H;

        uint4 buf[8];
        if (kc + 1 < GK / 32) {
            const int knext = (kc + 1) * 32;
#pragma unroll
            for (int t = 0; t < 4; t++) {
                buf[2 * t]     = *(const uint4*)(gsrc[t] + knext);
                buf[2 * t + 1] = *(const uint4*)(gsrc[t] + knext + 8);
            }
        }

#pragma unroll
        for (int ks = 0; ks < 2; ks++) {
            const int kcol = ks * 16 + c2;
            // A fragments (hi & lo), 4 m-frags
            uint32_t Afh[4][4], Afl[4][4];
#pragma unroll
            for (int mf = 0; mf < 4; mf++) {
                int off = (wm * 64 + mf * 16 + r2) * SROW + kcol;
                const __nv_bfloat16* ph = sb + off;                 // Ah tile
                const __nv_bfloat16* pl = sb + TILE_H + off;        // Al tile
                Afh[mf][0] = *(const uint32_t*)(ph);
                Afh[mf][1] = *(const uint32_t*)(ph + 8 * SROW);
                Afh[mf][2] = *(const uint32_t*)(ph + 8);
                Afh[mf][3] = *(const uint32_t*)(ph + 8 * SROW + 8);
                Afl[mf][0] = *(const uint32_t*)(pl);
                Afl[mf][1] = *(const uint32_t*)(pl + 8 * SROW);
                Afl[mf][2] = *(const uint32_t*)(pl + 8);
                Afl[mf][3] = *(const uint32_t*)(pl + 8 * SROW + 8);
            }
#pragma unroll
            for (int nf = 0; nf < 4; nf++) {
                int off = (wn * 32 + nf * 8 + r2) * SROW + kcol;
                const __nv_bfloat16* ph = sb + 2 * TILE_H + off;    // Bh tile
                const __nv_bfloat16* pl = sb + 3 * TILE_H + off;    // Bl tile
                uint32_t b0h = *(const uint32_t*)(ph);
                uint32_t b1h = *(const uint32_t*)(ph + 8);
                uint32_t b0l = *(const uint32_t*)(pl);
                uint32_t b1l = *(const uint32_t*)(pl + 8);
#pragma unroll
                for (int mf = 0; mf < 4; mf++) {
                    MMA_BF16(acc[mf][nf][0], acc[mf][nf][1], acc[mf][nf][2], acc[mf][nf][3],
                             Afh[mf][0], Afh[mf][1], Afh[mf][2], Afh[mf][3], b0h, b1h);
                    MMA_BF16(acc[mf][nf][0], acc[mf][nf][1], acc[mf][nf][2], acc[mf][nf][3],
                             Afh[mf][0], Afh[mf][1], Afh[mf][2], Afh[mf][3], b0l, b1l);
                    MMA_BF16(acc[mf][nf][0], acc[mf][nf][1], acc[mf][nf][2], acc[mf][nf][3],
                             Afl[mf][0], Afl[mf][1], Afl[mf][2], Afl[mf][3], b0h, b1h);
                }
            }
        }

        if (kc + 1 < GK / 32) {
            __syncthreads();   // everyone done reading stage 'next' from iter kc-1? (next==1-cur, last read at kc-1) -> safe to overwrite after this barrier
            __nv_bfloat16* sn = smem + (1 - cur) * STAGE_H;
#pragma unroll
            for (int t = 0; t < 4; t++) {
                *(uint4*)(sn + t * TILE_H + soff) = buf[2 * t];
                *(uint4*)(sn + t * TILE_H + soff + 8) = buf[2 * t + 1];
            }
            __syncthreads();
        }
    }

    // epilogue
#pragma unroll
    for (int mf = 0; mf < 4; mf++) {
        const int row = m0 + wm * 64 + mf * 16 + r2;
#pragma unroll
        for (int nf = 0; nf < 4; nf++) {
            float* cp0 = C + (size_t)row * ldc + coff + n0 + wn * 32 + nf * 8 + c2;
            *(float2*)cp0 = make_float2(acc[mf][nf][0], acc[mf][nf][1]);
            *(float2*)(cp0 + 8 * (size_t)ldc) = make_float2(acc[mf][nf][2], acc[mf][nf][3]);
        }
    }
}

// ---------------- RMSNorm over q part (1024 wide) ----------------
__global__ __launch_bounds__(256) void rms_q(const float* __restrict__ w)
{
    const int t = blockIdx.x;
    float* row = g_xqkv + (size_t)t * QKVW;
    const int tid = threadIdx.x;

    float v[4];
    float ss = 0.f;
#pragma unroll
    for (int i = 0; i < 4; i++) {
        v[i] = row[tid + 256 * i];
        ss = fmaf(v[i], v[i], ss);
    }
#pragma unroll
    for (int o = 16; o > 0; o >>= 1) ss += __shfl_xor_sync(0xffffffffu, ss, o);

    __shared__ float red[8];
    __shared__ float sscl;
    if ((tid & 31) == 0) red[tid >> 5] = ss;
    __syncthreads();
    if (tid == 0) {
        float tot = 0.f;
#pragma unroll
        for (int i = 0; i < 8; i++) tot += red[i];
        sscl = rsqrtf(tot * (1.f / 1024.f) + 1e-6f);
    }
    __syncthreads();
    float scl = sscl;
#pragma unroll
    for (int i = 0; i < 4; i++) {
        int idx = tid + 256 * i;
        row[idx] = v[i] * scl * w[idx];
    }
}

// ---------------- RMSNorm over k part (256 wide, at offset 1024) ----------------
__global__ __launch_bounds__(256) void rms_k(const float* __restrict__ w)
{
    const int t = blockIdx.x;
    float* row = g_xqkv + (size_t)t * QKVW + 1024;
    const int tid = threadIdx.x;

    float v = row[tid];
    float ss = v * v;
#pragma unroll
    for (int o = 16; o > 0; o >>= 1) ss += __shfl_xor_sync(0xffffffffu, ss, o);

    __shared__ float red[8];
    __shared__ float sscl;
    if ((tid & 31) == 0) red[tid >> 5] = ss;
    __syncthreads();
    if (tid == 0) {
        float tot = 0.f;
#pragma unroll
        for (int i = 0; i < 8; i++) tot += red[i];
        sscl = rsqrtf(tot * (1.f / 256.f) + 1e-6f);
    }
    __syncthreads();
    row[tid] = v * sscl * w[tid];
}

// ---------------- Attention ----------------
// grid: (S/64, NKV, B); block 256. thread = (gqa head 0..3) x (query 0..63).
__global__ __launch_bounds__(256) void attn_kernel()
{
    __shared__ float Ks[16][HD];
    __shared__ float Vs[16][HD];

    const int tid = threadIdx.x;
    const int qi = tid & 63;
    const int hl = tid >> 6;                 // 0..3
    const int kvh = blockIdx.y;
    const int b = blockIdx.z;
    const int head = kvh * 4 + hl;
    const int qstart = blockIdx.x * 64;
    const int qpos = qstart + qi;

    const float scale = 0.125f;              // 1/sqrt(64)
    const float slope = exp2f(-0.5f * (float)(head + 1));   // 2^(-8(h+1)/16)

    float q[HD];
    {
        const float* qp = g_xqkv + (size_t)(b * SS + qpos) * QKVW + head * HD;
#pragma unroll
        for (int d = 0; d < HD; d += 4) {
            float4 v = *(const float4*)(qp + d);
            q[d] = v.x * scale; q[d + 1] = v.y * scale;
            q[d + 2] = v.z * scale; q[d + 3] = v.w * scale;
        }
    }

    float o[HD];
#pragma unroll
    for (int d = 0; d < HD; d++) o[d] = 0.f;
    float m = -INFINITY, l = 0.f;

    int kstart = qstart - WIN; if (kstart < 0) kstart = 0;
    const int kend = qstart + 64;

    const int lrow = tid >> 4;               // 0..15
    const int lcol = (tid & 15) << 2;        // 0..60

    for (int kc = kstart; kc < kend; kc += 16) {
        {
            const float* base = g_xqkv + (size_t)(b * SS + kc + lrow) * QKVW;
            *(float4*)&Ks[lrow][lcol] = *(const float4*)(base + 1024 + kvh * HD + lcol);
            *(float4*)&Vs[lrow][lcol] = *(const float4*)(base + 1280 + kvh * HD + lcol);
        }
        __syncthreads();

        float s[16];
#pragma unroll
        for (int j = 0; j < 16; j++) {
            float acc = 0.f;
#pragma unroll
            for (int d = 0; d < HD; d += 4) {
                float4 kv = *(const float4*)&Ks[j][d];
                acc = fmaf(q[d],     kv.x, acc);
                acc = fmaf(q[d + 1], kv.y, acc);
                acc = fmaf(q[d + 2], kv.z, acc);
                acc = fmaf(q[d + 3], kv.w, acc);
            }
            int kpos = kc + j;
            bool ok = (kpos <= qpos) && (kpos + WIN >= qpos);
            s[j] = ok ? fmaf(slope, (float)(kpos - qpos), acc) : -INFINITY;
        }

        float cmax = s[0];
#pragma unroll
        for (int j = 1; j < 16; j++) cmax = fmaxf(cmax, s[j]);
        float m_new = fmaxf(m, cmax);

        if (m_new > -INFINITY) {
            float alpha = __expf(m - m_new);   // m=-inf -> 0
            l *= alpha;
#pragma unroll
            for (int d = 0; d < HD; d++) o[d] *= alpha;
#pragma unroll
            for (int j = 0; j < 16; j++) {
                float p = __expf(s[j] - m_new);  // masked -> 0
                l += p;
#pragma unroll
                for (int d = 0; d < HD; d += 4) {
                    float4 vv = *(const float4*)&Vs[j][d];
                    o[d]     = fmaf(p, vv.x, o[d]);
                    o[d + 1] = fmaf(p, vv.y, o[d + 1]);
                    o[d + 2] = fmaf(p, vv.z, o[d + 2]);
                    o[d + 3] = fmaf(p, vv.w, o[d + 3]);
                }
            }
            m = m_new;
        }
        __syncthreads();
    }

    float inv = 1.f / l;
    float* op = g_attn + (size_t)(b * SS + qpos) * DIM + head * HD;
#pragma unroll
    for (int d = 0; d < HD; d += 4) {
        float4 r = make_float4(o[d] * inv, o[d + 1] * inv, o[d + 2] * inv, o[d + 3] * inv);
        *(float4*)(op + d) = r;
    }
}

// ---------------- launch ----------------
extern "C" void kernel_launch(void* const* d_in, const int* in_sizes, int n_in,
                              void* d_out, int out_size)
{
    const float* x  = (const float*)d_in[0];
    const float* wq = (const float*)d_in[1];
    const float* wk = (const float*)d_in[2];
    const float* wv = (const float*)d_in[3];
    const float* wo = (const float*)d_in[4];
    const float* qw = (const float*)d_in[5];
    const float* kw = (const float*)d_in[6];
    float* out = (float*)d_out;

    float* xqkv = nullptr;
    float* attn = nullptr;
    __nv_bfloat16 *ah = nullptr, *al = nullptr, *wh = nullptr, *wl = nullptr;
    cudaGetSymbolAddress((void**)&xqkv, g_xqkv);
    cudaGetSymbolAddress((void**)&attn, g_attn);
    cudaGetSymbolAddress((void**)&ah, g_ah);
    cudaGetSymbolAddress((void**)&al, g_al);
    cudaGetSymbolAddress((void**)&wh, g_wh);
    cudaGetSymbolAddress((void**)&wl, g_wl);

    static bool attr_done = false;
    if (!attr_done) {
        cudaFuncSetAttribute(hmma_gemm, cudaFuncAttributeMaxDynamicSharedMemorySize, GEMM_SMEM);
        attr_done = true;
    }

    // hi/lo splits (weights stacked: wq rows 0-1023 | wk 1024-1279 | wv 1280-1535 | wo 1536-2559)
    split_bf16<<<(TT * DIM / 4) / 256, 256>>>(x, ah, al, TT * DIM / 4);
    split_bf16<<<(1024 * 1024 / 4) / 256, 256>>>(wq, wh + WQ_ROW * DIM, wl + WQ_ROW * DIM, 1024 * 1024 / 4);
    split_bf16<<<(256 * 1024 / 4) / 256, 256>>>(wk, wh + WK_ROW * DIM, wl + WK_ROW * DIM, 256 * 1024 / 4);
    split_bf16<<<(256 * 1024 / 4) / 256, 256>>>(wv, wh + WV_ROW * DIM, wl + WV_ROW * DIM, 256 * 1024 / 4);
    split_bf16<<<(1024 * 1024 / 4) / 256, 256>>>(wo, wh + WO_ROW * DIM, wl + WO_ROW * DIM, 1024 * 1024 / 4);

    // merged QKV projection: one GEMM, N=1536
    hmma_gemm<<<dim3(QKVW / 128, TT / 128), 256, GEMM_SMEM>>>(
        ah, al, wh, wl, xqkv, QKVW, 0);

    rms_q<<<TT, 256>>>(qw);
    rms_k<<<TT, 256>>>(kw);

    attn_kernel<<<dim3(SS / 64, NKV, BB), 256>>>();

    // output projection (reuse activation hi/lo buffers)
    split_bf16<<<(TT * DIM / 4) / 256, 256>>>(attn, ah, al, TT * DIM / 4);
    hmma_gemm<<<dim3(DIM / 128, TT / 128), 256, GEMM_SMEM>>>(
        ah, al, wh + (size_t)WO_ROW * DIM, wl + (size_t)WO_ROW * DIM, out, DIM, 0);
}

// round 4
// speedup vs baseline: 2.6112x; 1.8177x over previous
#include <cuda_runtime.h>
#include <cuda_bf16.h>
#include <math.h>
#include <stdint.h>

#define DIM   1024
#define NH    16
#define NKV   4
#define HD    64
#define WIN   512
#define BB    2
#define SS    2048
#define TT    (BB*SS)
#define QKVW  1536   // 1024 q | 256 k | 256 v per token
#define GK    1024   // K dim of every GEMM

// ---------------- scratch (no allocs allowed) ----------------
__device__ float g_xqkv[(size_t)TT * QKVW];          // fp32 qkv projections
__device__ __nv_bfloat16 g_ah[(size_t)TT * DIM];     // activation hi (x, then attn out)
__device__ __nv_bfloat16 g_al[(size_t)TT * DIM];     // activation lo
__device__ __nv_bfloat16 g_wh[(size_t)2560 * DIM];   // weights hi: wq|wk|wv|wo
__device__ __nv_bfloat16 g_wl[(size_t)2560 * DIM];
__device__ __nv_bfloat16 g_qh[(size_t)TT * DIM];     // per-head Q hi  [(b*NH+h)*SS+s][64]
__device__ __nv_bfloat16 g_ql[(size_t)TT * DIM];
__device__ __nv_bfloat16 g_kh[(size_t)TT * 256];     // per-kvhead K hi [(b*NKV+kv)*SS+s][64]
__device__ __nv_bfloat16 g_kl[(size_t)TT * 256];
__device__ __nv_bfloat16 g_vh[(size_t)TT * 256];
__device__ __nv_bfloat16 g_vl[(size_t)TT * 256];
#define WQ_ROW 0
#define WK_ROW 1024
#define WV_ROW 1280
#define WO_ROW 1536

// ---------------- small PTX helpers ----------------
__device__ __forceinline__ uint32_t smem_u32(const void* p) {
    uint32_t a;
    asm("{ .reg .u64 t; cvta.to.shared.u64 t, %1; cvt.u32.u64 %0, t; }" : "=r"(a) : "l"(p));
    return a;
}
__device__ __forceinline__ void cp16(uint32_t s, const void* g) {
    asm volatile("{ .reg .u64 gg; cvta.to.global.u64 gg, %1; cp.async.cg.shared.global [%0], [gg], 16; }"
                 :: "r"(s), "l"(g) : "memory");
}
__device__ __forceinline__ void cp_commit() { asm volatile("cp.async.commit_group;" ::: "memory"); }
template <int N>
__device__ __forceinline__ void cp_wait() { asm volatile("cp.async.wait_group %0;" :: "n"(N) : "memory"); }

__device__ __forceinline__ uint32_t packbf(float lo, float hi) {
    uint32_t r;
    asm("cvt.rn.bf16x2.f32 %0, %1, %2;" : "=r"(r) : "f"(hi), "f"(lo));
    return r;
}

#define MMA_BF16(c0,c1,c2,c3, a0,a1,a2,a3, b0,b1) \
    asm volatile("mma.sync.aligned.m16n8k16.row.col.f32.bf16.bf16.f32 " \
                 "{%0,%1,%2,%3}, {%4,%5,%6,%7}, {%8,%9}, {%0,%1,%2,%3};" \
                 : "+f"(c0), "+f"(c1), "+f"(c2), "+f"(c3) \
                 : "r"(a0), "r"(a1), "r"(a2), "r"(a3), "r"(b0), "r"(b1))

#define LDMX4(r0,r1,r2,r3, addr) \
    asm volatile("ldmatrix.sync.aligned.m8n8.x4.shared.b16 {%0,%1,%2,%3}, [%4];" \
                 : "=r"(r0), "=r"(r1), "=r"(r2), "=r"(r3) : "r"(addr))
#define LDMX4T(r0,r1,r2,r3, addr) \
    asm volatile("ldmatrix.sync.aligned.m8n8.x4.trans.shared.b16 {%0,%1,%2,%3}, [%4];" \
                 : "=r"(r0), "=r"(r1), "=r"(r2), "=r"(r3) : "r"(addr))

// ---------------- fp32 -> bf16 hi/lo split ----------------
__global__ __launch_bounds__(256) void split_bf16(
    const float* __restrict__ in, __nv_bfloat16* __restrict__ hi,
    __nv_bfloat16* __restrict__ lo, int n4)
{
    int i = blockIdx.x * 256 + threadIdx.x;
    if (i >= n4) return;
    float4 v = ((const float4*)in)[i];
    float f[4] = {v.x, v.y, v.z, v.w};
    union { __nv_bfloat16 b[4]; uint2 u; } H, L;
#pragma unroll
    for (int k = 0; k < 4; k++) {
        __nv_bfloat16 h = __float2bfloat16(f[k]);
        H.b[k] = h;
        L.b[k] = __float2bfloat16(f[k] - __bfloat162float(h));
    }
    ((uint2*)hi)[i] = H.u;
    ((uint2*)lo)[i] = L.u;
}

// ---------------- HMMA split-bf16 GEMM (round-3, unchanged) ----------------
#define SROW 40
#define TILE_H (128 * SROW)
#define STAGE_H (4 * TILE_H)
#define GEMM_SMEM (2 * STAGE_H * 2)

__global__ __launch_bounds__(256) void hmma_gemm(
    const __nv_bfloat16* __restrict__ ah, const __nv_bfloat16* __restrict__ al,
    const __nv_bfloat16* __restrict__ bh, const __nv_bfloat16* __restrict__ bl,
    float* __restrict__ C, int ldc, int coff)
{
    extern __shared__ __nv_bfloat16 smem[];

    const int tid = threadIdx.x;
    const int wid = tid >> 5;
    const int lid = tid & 31;
    const int wm = wid & 1;
    const int wn = wid >> 1;
    const int m0 = blockIdx.y * 128;
    const int n0 = blockIdx.x * 128;

    const int grow = tid >> 1;
    const int gcp = (tid & 1) * 16;

    const __nv_bfloat16* gsrc[4];
    gsrc[0] = ah + (size_t)(m0 + grow) * GK + gcp;
    gsrc[1] = al + (size_t)(m0 + grow) * GK + gcp;
    gsrc[2] = bh + (size_t)(n0 + grow) * GK + gcp;
    gsrc[3] = bl + (size_t)(n0 + grow) * GK + gcp;
    const int soff = grow * SROW + gcp;

    float acc[4][4][4];
#pragma unroll
    for (int i = 0; i < 4; i++)
#pragma unroll
        for (int j = 0; j < 4; j++)
#pragma unroll
            for (int k = 0; k < 4; k++) acc[i][j][k] = 0.f;

    const int r2 = lid >> 2;
    const int c2 = (lid & 3) * 2;

#pragma unroll
    for (int t = 0; t < 4; t++) {
        uint4 v0 = *(const uint4*)(gsrc[t]);
        uint4 v1 = *(const uint4*)(gsrc[t] + 8);
        *(uint4*)(smem + t * TILE_H + soff) = v0;
        *(uint4*)(smem + t * TILE_H + soff + 8) = v1;
    }
    __syncthreads();

    for (int kc = 0; kc < GK / 32; kc++) {
        const int cur = kc & 1;
        const __nv_bfloat16* sb = smem + cur * STAGE_H;

        uint4 buf[8];
        if (kc + 1 < GK / 32) {
            const int knext = (kc + 1) * 32;
#pragma unroll
            for (int t = 0; t < 4; t++) {
                buf[2 * t]     = *(const uint4*)(gsrc[t] + knext);
                buf[2 * t + 1] = *(const uint4*)(gsrc[t] + knext + 8);
            }
        }

#pragma unroll
        for (int ks = 0; ks < 2; ks++) {
            const int kcol = ks * 16 + c2;
            uint32_t Afh[4][4], Afl[4][4];
#pragma unroll
            for (int mf = 0; mf < 4; mf++) {
                int off = (wm * 64 + mf * 16 + r2) * SROW + kcol;
                const __nv_bfloat16* ph = sb + off;
                const __nv_bfloat16* pl = sb + TILE_H + off;
                Afh[mf][0] = *(const uint32_t*)(ph);
                Afh[mf][1] = *(const uint32_t*)(ph + 8 * SROW);
                Afh[mf][2] = *(const uint32_t*)(ph + 8);
                Afh[mf][3] = *(const uint32_t*)(ph + 8 * SROW + 8);
                Afl[mf][0] = *(const uint32_t*)(pl);
                Afl[mf][1] = *(const uint32_t*)(pl + 8 * SROW);
                Afl[mf][2] = *(const uint32_t*)(pl + 8);
                Afl[mf][3] = *(const uint32_t*)(pl + 8 * SROW + 8);
            }
#pragma unroll
            for (int nf = 0; nf < 4; nf++) {
                int off = (wn * 32 + nf * 8 + r2) * SROW + kcol;
                const __nv_bfloat16* ph = sb + 2 * TILE_H + off;
                const __nv_bfloat16* pl = sb + 3 * TILE_H + off;
                uint32_t b0h = *(const uint32_t*)(ph);
                uint32_t b1h = *(const uint32_t*)(ph + 8);
                uint32_t b0l = *(const uint32_t*)(pl);
                uint32_t b1l = *(const uint32_t*)(pl + 8);
#pragma unroll
                for (int mf = 0; mf < 4; mf++) {
                    MMA_BF16(acc[mf][nf][0], acc[mf][nf][1], acc[mf][nf][2], acc[mf][nf][3],
                             Afh[mf][0], Afh[mf][1], Afh[mf][2], Afh[mf][3], b0h, b1h);
                    MMA_BF16(acc[mf][nf][0], acc[mf][nf][1], acc[mf][nf][2], acc[mf][nf][3],
                             Afh[mf][0], Afh[mf][1], Afh[mf][2], Afh[mf][3], b0l, b1l);
                    MMA_BF16(acc[mf][nf][0], acc[mf][nf][1], acc[mf][nf][2], acc[mf][nf][3],
                             Afl[mf][0], Afl[mf][1], Afl[mf][2], Afl[mf][3], b0h, b1h);
                }
            }
        }

        if (kc + 1 < GK / 32) {
            __syncthreads();
            __nv_bfloat16* sn = smem + (1 - cur) * STAGE_H;
#pragma unroll
            for (int t = 0; t < 4; t++) {
                *(uint4*)(sn + t * TILE_H + soff) = buf[2 * t];
                *(uint4*)(sn + t * TILE_H + soff + 8) = buf[2 * t + 1];
            }
            __syncthreads();
        }
    }

#pragma unroll
    for (int mf = 0; mf < 4; mf++) {
        const int row = m0 + wm * 64 + mf * 16 + r2;
#pragma unroll
        for (int nf = 0; nf < 4; nf++) {
            float* cp0 = C + (size_t)row * ldc + coff + n0 + wn * 32 + nf * 8 + c2;
            *(float2*)cp0 = make_float2(acc[mf][nf][0], acc[mf][nf][1]);
            *(float2*)(cp0 + 8 * (size_t)ldc) = make_float2(acc[mf][nf][2], acc[mf][nf][3]);
        }
    }
}

// ---------------- RMSNorm q -> per-head bf16 hi/lo (scale folded) ----------------
__global__ __launch_bounds__(256) void rms_q(const float* __restrict__ w)
{
    const int t = blockIdx.x;
    const int b = t >> 11, s = t & (SS - 1);
    const float* row = g_xqkv + (size_t)t * QKVW;
    const int tid = threadIdx.x;

    float v[4];
    float ss = 0.f;
#pragma unroll
    for (int i = 0; i < 4; i++) {
        v[i] = row[tid + 256 * i];
        ss = fmaf(v[i], v[i], ss);
    }
#pragma unroll
    for (int o = 16; o > 0; o >>= 1) ss += __shfl_xor_sync(0xffffffffu, ss, o);

    __shared__ float red[8];
    __shared__ float sscl;
    if ((tid & 31) == 0) red[tid >> 5] = ss;
    __syncthreads();
    if (tid == 0) {
        float tot = 0.f;
#pragma unroll
        for (int i = 0; i < 8; i++) tot += red[i];
        sscl = rsqrtf(tot * (1.f / 1024.f) + 1e-6f);
    }
    __syncthreads();
    float scl = sscl * 0.125f;   // fold 1/sqrt(64)
#pragma unroll
    for (int i = 0; i < 4; i++) {
        int idx = tid + 256 * i;
        float val = v[i] * scl * w[idx];
        int head = idx >> 6, d = idx & 63;
        size_t off = ((size_t)(b * NH + head) * SS + s) * 64 + d;
        __nv_bfloat16 h = __float2bfloat16(val);
        g_qh[off] = h;
        g_ql[off] = __float2bfloat16(val - __bfloat162float(h));
    }
}

// ---------------- K rmsnorm + V split -> per-kvhead bf16 hi/lo ----------------
__global__ __launch_bounds__(256) void prep_kv(const float* __restrict__ kw)
{
    const int t = blockIdx.x;
    const int b = t >> 11, s = t & (SS - 1);
    const float* row = g_xqkv + (size_t)t * QKVW;
    const int tid = threadIdx.x;
    const int kv = tid >> 6, d = tid & 63;
    const size_t off = ((size_t)(b * NKV + kv) * SS + s) * 64 + d;

    float kvl = row[1024 + tid];
    float ss = kvl * kvl;
#pragma unroll
    for (int o = 16; o > 0; o >>= 1) ss += __shfl_xor_sync(0xffffffffu, ss, o);

    __shared__ float red[8];
    __shared__ float sscl;
    if ((tid & 31) == 0) red[tid >> 5] = ss;
    __syncthreads();
    if (tid == 0) {
        float tot = 0.f;
#pragma unroll
        for (int i = 0; i < 8; i++) tot += red[i];
        sscl = rsqrtf(tot * (1.f / 256.f) + 1e-6f);
    }
    __syncthreads();

    float kn = kvl * sscl * kw[tid];
    __nv_bfloat16 kh = __float2bfloat16(kn);
    g_kh[off] = kh;
    g_kl[off] = __float2bfloat16(kn - __bfloat162float(kh));

    float vv = row[1280 + tid];
    __nv_bfloat16 vh = __float2bfloat16(vv);
    g_vh[off] = vh;
    g_vl[off] = __float2bfloat16(vv - __bfloat162float(vh));
}

// ---------------- tensor-core attention ----------------
// grid (S/128, NH, B), 256 threads = 8 warps, warp = 16 query rows.
// smem: 2 stages x 4 tiles (Kh,Kl,Vh,Vl), tile = 64 keys x 72 halves (144B rows).
#define TILEB 9216                    // 64*144
#define ATT_SMEM (2 * 4 * TILEB)      // 73728

__global__ __launch_bounds__(256, 2) void attn_tc()
{
    extern __shared__ char asm_[];
    const uint32_t smb = smem_u32(asm_);

    const int tid = threadIdx.x;
    const int wid = tid >> 5;
    const int lid = tid & 31;
    const int qstart = blockIdx.x * 128;
    const int head = blockIdx.y;
    const int b = blockIdx.z;
    const int kvh = head >> 2;

    const int r = lid >> 2;
    const int c2 = (lid & 3) * 2;
    const int qpos0 = qstart + wid * 16 + r;
    const float slope = exp2f(-0.5f * (float)(head + 1));

    // resident Q hi fragments
    const __nv_bfloat16* qbh = g_qh + ((size_t)(b * NH + head) * SS + qstart + wid * 16) * 64;
    const __nv_bfloat16* qbl = g_ql + ((size_t)(b * NH + head) * SS + qstart + wid * 16) * 64;
    uint32_t Qh[4][4];
#pragma unroll
    for (int ks = 0; ks < 4; ks++) {
        Qh[ks][0] = *(const uint32_t*)(qbh + r * 64 + ks * 16 + c2);
        Qh[ks][1] = *(const uint32_t*)(qbh + (r + 8) * 64 + ks * 16 + c2);
        Qh[ks][2] = *(const uint32_t*)(qbh + r * 64 + ks * 16 + 8 + c2);
        Qh[ks][3] = *(const uint32_t*)(qbh + (r + 8) * 64 + ks * 16 + 8 + c2);
    }

    float O[8][4];
#pragma unroll
    for (int i = 0; i < 8; i++)
#pragma unroll
        for (int j = 0; j < 4; j++) O[i][j] = 0.f;
    float m0 = -INFINITY, m1 = -INFINITY, l0 = 0.f, l1 = 0.f;

    const int kc0 = (qstart >= WIN) ? qstart - WIN : 0;
    const int nch = (qstart + 128 - kc0) >> 6;

    // cp.async mapping: thread -> key row, 16B segment
    const int key_ld = tid >> 2;
    const int seg = tid & 3;
    const __nv_bfloat16* src_base[4];
    {
        size_t kvb = ((size_t)(b * NKV + kvh) * SS) * 64;
        src_base[0] = g_kh + kvb; src_base[1] = g_kl + kvb;
        src_base[2] = g_vh + kvb; src_base[3] = g_vl + kvb;
    }
    auto load_chunk = [&](int kc, int stg) {
        uint32_t sb = smb + stg * 4 * TILEB + key_ld * 144 + seg * 16;
#pragma unroll
        for (int t = 0; t < 4; t++) {
            const __nv_bfloat16* src = src_base[t] + (size_t)(kc + key_ld) * 64 + seg * 8;
            cp16(sb + t * TILEB, src);
            cp16(sb + t * TILEB + 64, src + 32);
        }
        cp_commit();
    };

    load_chunk(kc0, 0);
    if (nch > 1) load_chunk(kc0 + 64, 1);

    const uint32_t lane_off = (uint32_t)(((lid >> 4) * 8 + (lid & 7)) * 144 + ((lid >> 3) & 1) * 16);

    for (int c = 0; c < nch; c++) {
        if (c < nch - 1) cp_wait<1>(); else cp_wait<0>();
        __syncthreads();

        const uint32_t sb = smb + (c & 1) * 4 * TILEB;
        const int kc = kc0 + c * 64;

        // ---- scores: S = Qh*Kh + Qh*Kl + Ql*Kh ----
        float S[8][4];
#pragma unroll
        for (int i = 0; i < 8; i++)
#pragma unroll
            for (int j = 0; j < 4; j++) S[i][j] = 0.f;

#pragma unroll
        for (int ks = 0; ks < 4; ks++) {
            uint32_t Qlr[4];
            Qlr[0] = *(const uint32_t*)(qbl + r * 64 + ks * 16 + c2);
            Qlr[1] = *(const uint32_t*)(qbl + (r + 8) * 64 + ks * 16 + c2);
            Qlr[2] = *(const uint32_t*)(qbl + r * 64 + ks * 16 + 8 + c2);
            Qlr[3] = *(const uint32_t*)(qbl + (r + 8) * 64 + ks * 16 + 8 + c2);
#pragma unroll
            for (int nfp = 0; nfp < 4; nfp++) {
                uint32_t kh0, kh1, kh2, kh3, kl0, kl1, kl2, kl3;
                LDMX4(kh0, kh1, kh2, kh3, sb + nfp * 2304 + ks * 32 + lane_off);
                LDMX4(kl0, kl1, kl2, kl3, sb + TILEB + nfp * 2304 + ks * 32 + lane_off);
                MMA_BF16(S[2*nfp][0], S[2*nfp][1], S[2*nfp][2], S[2*nfp][3],
                         Qh[ks][0], Qh[ks][1], Qh[ks][2], Qh[ks][3], kh0, kh1);
                MMA_BF16(S[2*nfp+1][0], S[2*nfp+1][1], S[2*nfp+1][2], S[2*nfp+1][3],
                         Qh[ks][0], Qh[ks][1], Qh[ks][2], Qh[ks][3], kh2, kh3);
                MMA_BF16(S[2*nfp][0], S[2*nfp][1], S[2*nfp][2], S[2*nfp][3],
                         Qh[ks][0], Qh[ks][1], Qh[ks][2], Qh[ks][3], kl0, kl1);
                MMA_BF16(S[2*nfp+1][0], S[2*nfp+1][1], S[2*nfp+1][2], S[2*nfp+1][3],
                         Qh[ks][0], Qh[ks][1], Qh[ks][2], Qh[ks][3], kl2, kl3);
                MMA_BF16(S[2*nfp][0], S[2*nfp][1], S[2*nfp][2], S[2*nfp][3],
                         Qlr[0], Qlr[1], Qlr[2], Qlr[3], kh0, kh1);
                MMA_BF16(S[2*nfp+1][0], S[2*nfp+1][1], S[2*nfp+1][2], S[2*nfp+1][3],
                         Qlr[0], Qlr[1], Qlr[2], Qlr[3], kh2, kh3);
            }
        }

        // ---- bias + mask ----
#pragma unroll
        for (int nf = 0; nf < 8; nf++) {
            int rel0 = kc + nf * 8 + c2 - qpos0;
            int rel2 = rel0 - 8;
            S[nf][0] = (rel0     <= 0 && rel0     >= -WIN) ? fmaf(slope, (float)rel0,     S[nf][0]) : -INFINITY;
            S[nf][1] = (rel0 + 1 <= 0 && rel0 + 1 >= -WIN) ? fmaf(slope, (float)(rel0+1), S[nf][1]) : -INFINITY;
            S[nf][2] = (rel2     <= 0 && rel2     >= -WIN) ? fmaf(slope, (float)rel2,     S[nf][2]) : -INFINITY;
            S[nf][3] = (rel2 + 1 <= 0 && rel2 + 1 >= -WIN) ? fmaf(slope, (float)(rel2+1), S[nf][3]) : -INFINITY;
        }

        // ---- online softmax ----
        float mx0 = -INFINITY, mx1 = -INFINITY;
#pragma unroll
        for (int nf = 0; nf < 8; nf++) {
            mx0 = fmaxf(mx0, fmaxf(S[nf][0], S[nf][1]));
            mx1 = fmaxf(mx1, fmaxf(S[nf][2], S[nf][3]));
        }
        mx0 = fmaxf(mx0, __shfl_xor_sync(0xffffffffu, mx0, 1));
        mx0 = fmaxf(mx0, __shfl_xor_sync(0xffffffffu, mx0, 2));
        mx1 = fmaxf(mx1, __shfl_xor_sync(0xffffffffu, mx1, 1));
        mx1 = fmaxf(mx1, __shfl_xor_sync(0xffffffffu, mx1, 2));

        float mn0 = fmaxf(fmaxf(m0, mx0), -1e30f);
        float mn1 = fmaxf(fmaxf(m1, mx1), -1e30f);
        float a0 = __expf(m0 - mn0);
        float a1 = __expf(m1 - mn1);
        m0 = mn0; m1 = mn1;
        l0 *= a0; l1 *= a1;
#pragma unroll
        for (int nf = 0; nf < 8; nf++) {
            O[nf][0] *= a0; O[nf][1] *= a0;
            O[nf][2] *= a1; O[nf][3] *= a1;
        }
#pragma unroll
        for (int nf = 0; nf < 8; nf++) {
            S[nf][0] = __expf(S[nf][0] - m0);
            S[nf][1] = __expf(S[nf][1] - m0);
            S[nf][2] = __expf(S[nf][2] - m1);
            S[nf][3] = __expf(S[nf][3] - m1);
            l0 += S[nf][0] + S[nf][1];
            l1 += S[nf][2] + S[nf][3];
        }

        // ---- PV: O += P*Vh + P*Vl ----
#pragma unroll
        for (int ks = 0; ks < 4; ks++) {
            uint32_t pa0 = packbf(S[2*ks][0],   S[2*ks][1]);
            uint32_t pa1 = packbf(S[2*ks][2],   S[2*ks][3]);
            uint32_t pa2 = packbf(S[2*ks+1][0], S[2*ks+1][1]);
            uint32_t pa3 = packbf(S[2*ks+1][2], S[2*ks+1][3]);
#pragma unroll
            for (int nfp = 0; nfp < 4; nfp++) {
                uint32_t v0, v1, v2, v3, w0, w1, w2, w3;
                LDMX4T(v0, v1, v2, v3, sb + 2 * TILEB + ks * 2304 + nfp * 32 + lane_off);
                LDMX4T(w0, w1, w2, w3, sb + 3 * TILEB + ks * 2304 + nfp * 32 + lane_off);
                MMA_BF16(O[2*nfp][0], O[2*nfp][1], O[2*nfp][2], O[2*nfp][3],
                         pa0, pa1, pa2, pa3, v0, v2);
                MMA_BF16(O[2*nfp+1][0], O[2*nfp+1][1], O[2*nfp+1][2], O[2*nfp+1][3],
                         pa0, pa1, pa2, pa3, v1, v3);
                MMA_BF16(O[2*nfp][0], O[2*nfp][1], O[2*nfp][2], O[2*nfp][3],
                         pa0, pa1, pa2, pa3, w0, w2);
                MMA_BF16(O[2*nfp+1][0], O[2*nfp+1][1], O[2*nfp+1][2], O[2*nfp+1][3],
                         pa0, pa1, pa2, pa3, w1, w3);
            }
        }

        __syncthreads();
        if (c + 2 < nch) load_chunk(kc0 + (c + 2) * 64, c & 1);
    }

    // ---- epilogue ----
    l0 += __shfl_xor_sync(0xffffffffu, l0, 1);
    l0 += __shfl_xor_sync(0xffffffffu, l0, 2);
    l1 += __shfl_xor_sync(0xffffffffu, l1, 1);
    l1 += __shfl_xor_sync(0xffffffffu, l1, 2);
    float inv0 = 1.f / l0, inv1 = 1.f / l1;

    size_t out0 = ((size_t)(b * SS + qpos0) * DIM) + head * 64;
    size_t out1 = out0 + (size_t)8 * DIM;
#pragma unroll
    for (int nf = 0; nf < 8; nf++) {
        float y0 = O[nf][0] * inv0, y1 = O[nf][1] * inv0;
        float y2 = O[nf][2] * inv1, y3 = O[nf][3] * inv1;
        int col = nf * 8 + c2;
        __nv_bfloat16 h0 = __float2bfloat16(y0), h1 = __float2bfloat16(y1);
        __nv_bfloat16 h2 = __float2bfloat16(y2), h3 = __float2bfloat16(y3);
        *(uint32_t*)(g_ah + out0 + col) = packbf(__bfloat162float(h0) * 0.f + 0.f, 0.f) * 0 +
            ((uint32_t)__bfloat16_as_ushort(h0) | ((uint32_t)__bfloat16_as_ushort(h1) << 16));
        *(uint32_t*)(g_al + out0 + col) =
            ((uint32_t)__bfloat16_as_ushort(__float2bfloat16(y0 - __bfloat162float(h0))) |
             ((uint32_t)__bfloat16_as_ushort(__float2bfloat16(y1 - __bfloat162float(h1))) << 16));
        *(uint32_t*)(g_ah + out1 + col) =
            ((uint32_t)__bfloat16_as_ushort(h2) | ((uint32_t)__bfloat16_as_ushort(h3) << 16));
        *(uint32_t*)(g_al + out1 + col) =
            ((uint32_t)__bfloat16_as_ushort(__float2bfloat16(y2 - __bfloat162float(h2))) |
             ((uint32_t)__bfloat16_as_ushort(__float2bfloat16(y3 - __bfloat162float(h3))) << 16));
    }
}

// ---------------- launch ----------------
extern "C" void kernel_launch(void* const* d_in, const int* in_sizes, int n_in,
                              void* d_out, int out_size)
{
    const float* x  = (const float*)d_in[0];
    const float* wq = (const float*)d_in[1];
    const float* wk = (const float*)d_in[2];
    const float* wv = (const float*)d_in[3];
    const float* wo = (const float*)d_in[4];
    const float* qw = (const float*)d_in[5];
    const float* kw = (const float*)d_in[6];
    float* out = (float*)d_out;

    float* xqkv = nullptr;
    __nv_bfloat16 *ah = nullptr, *al = nullptr, *wh = nullptr, *wl = nullptr;
    cudaGetSymbolAddress((void**)&xqkv, g_xqkv);
    cudaGetSymbolAddress((void**)&ah, g_ah);
    cudaGetSymbolAddress((void**)&al, g_al);
    cudaGetSymbolAddress((void**)&wh, g_wh);
    cudaGetSymbolAddress((void**)&wl, g_wl);

    static bool attr_done = false;
    if (!attr_done) {
        cudaFuncSetAttribute(hmma_gemm, cudaFuncAttributeMaxDynamicSharedMemorySize, GEMM_SMEM);
        cudaFuncSetAttribute(attn_tc, cudaFuncAttributeMaxDynamicSharedMemorySize, ATT_SMEM);
        attr_done = true;
    }

    split_bf16<<<(TT * DIM / 4) / 256, 256>>>(x, ah, al, TT * DIM / 4);
    split_bf16<<<(1024 * 1024 / 4) / 256, 256>>>(wq, wh + WQ_ROW * DIM, wl + WQ_ROW * DIM, 1024 * 1024 / 4);
    split_bf16<<<(256 * 1024 / 4) / 256, 256>>>(wk, wh + WK_ROW * DIM, wl + WK_ROW * DIM, 256 * 1024 / 4);
    split_bf16<<<(256 * 1024 / 4) / 256, 256>>>(wv, wh + WV_ROW * DIM, wl + WV_ROW * DIM, 256 * 1024 / 4);
    split_bf16<<<(1024 * 1024 / 4) / 256, 256>>>(wo, wh + WO_ROW * DIM, wl + WO_ROW * DIM, 1024 * 1024 / 4);

    // merged QKV projection
    hmma_gemm<<<dim3(QKVW / 128, TT / 128), 256, GEMM_SMEM>>>(ah, al, wh, wl, xqkv, QKVW, 0);

    rms_q<<<TT, 256>>>(qw);
    prep_kv<<<TT, 256>>>(kw);

    attn_tc<<<dim3(SS / 128, NH, BB), 256, ATT_SMEM>>>();

    // output projection (attention wrote g_ah/g_al directly)
    hmma_gemm<<<dim3(DIM / 128, TT / 128), 256, GEMM_SMEM>>>(
        ah, al, wh + (size_t)WO_ROW * DIM, wl + (size_t)WO_ROW * DIM, out, DIM, 0);
}

// round 5
// speedup vs baseline: 2.9274x; 1.1211x over previous
#include <cuda_runtime.h>
#include <cuda_bf16.h>
#include <math.h>
#include <stdint.h>

#define DIM   1024
#define NH    16
#define NKV   4
#define HD    64
#define WIN   512
#define BB    2
#define SS    2048
#define TT    (BB*SS)
#define QKVW  1536   // 1024 q | 256 k | 256 v per token
#define GK    1024   // K dim of every GEMM

// ---------------- scratch (no allocs allowed) ----------------
__device__ float g_xqkv[(size_t)TT * QKVW];          // fp32 qkv projections
__device__ __nv_bfloat16 g_ah[(size_t)TT * DIM];     // activation hi (x, then attn out)
__device__ __nv_bfloat16 g_al[(size_t)TT * DIM];     // activation lo
__device__ __nv_bfloat16 g_wh[(size_t)2560 * DIM];   // weights hi: wq|wk|wv|wo
__device__ __nv_bfloat16 g_wl[(size_t)2560 * DIM];
__device__ __nv_bfloat16 g_qh[(size_t)TT * DIM];     // per-head Q hi  [(b*NH+h)*SS+s][64]
__device__ __nv_bfloat16 g_ql[(size_t)TT * DIM];
__device__ __nv_bfloat16 g_kh[(size_t)TT * 256];     // per-kvhead K hi [(b*NKV+kv)*SS+s][64]
__device__ __nv_bfloat16 g_kl[(size_t)TT * 256];
__device__ __nv_bfloat16 g_vh[(size_t)TT * 256];
__device__ __nv_bfloat16 g_vl[(size_t)TT * 256];
#define WQ_ROW 0
#define WK_ROW 1024
#define WV_ROW 1280
#define WO_ROW 1536

// ---------------- small PTX helpers ----------------
__device__ __forceinline__ uint32_t smem_u32(const void* p) {
    uint32_t a;
    asm("{ .reg .u64 t; cvta.to.shared.u64 t, %1; cvt.u32.u64 %0, t; }" : "=r"(a) : "l"(p));
    return a;
}
__device__ __forceinline__ void cp16(uint32_t s, const void* g) {
    asm volatile("{ .reg .u64 gg; cvta.to.global.u64 gg, %1; cp.async.cg.shared.global [%0], [gg], 16; }"
                 :: "r"(s), "l"(g) : "memory");
}
__device__ __forceinline__ void cp_commit() { asm volatile("cp.async.commit_group;" ::: "memory"); }
template <int N>
__device__ __forceinline__ void cp_wait() { asm volatile("cp.async.wait_group %0;" :: "n"(N) : "memory"); }

__device__ __forceinline__ uint32_t packbf(float lo, float hi) {
    uint32_t r;
    asm("cvt.rn.bf16x2.f32 %0, %1, %2;" : "=r"(r) : "f"(hi), "f"(lo));
    return r;
}

#define MMA_BF16(c0,c1,c2,c3, a0,a1,a2,a3, b0,b1) \
    asm volatile("mma.sync.aligned.m16n8k16.row.col.f32.bf16.bf16.f32 " \
                 "{%0,%1,%2,%3}, {%4,%5,%6,%7}, {%8,%9}, {%0,%1,%2,%3};" \
                 : "+f"(c0), "+f"(c1), "+f"(c2), "+f"(c3) \
                 : "r"(a0), "r"(a1), "r"(a2), "r"(a3), "r"(b0), "r"(b1))

#define LDMX4(r0,r1,r2,r3, addr) \
    asm volatile("ldmatrix.sync.aligned.m8n8.x4.shared.b16 {%0,%1,%2,%3}, [%4];" \
                 : "=r"(r0), "=r"(r1), "=r"(r2), "=r"(r3) : "r"(addr))
#define LDMX4T(r0,r1,r2,r3, addr) \
    asm volatile("ldmatrix.sync.aligned.m8n8.x4.trans.shared.b16 {%0,%1,%2,%3}, [%4];" \
                 : "=r"(r0), "=r"(r1), "=r"(r2), "=r"(r3) : "r"(addr))

// ---------------- fp32 -> bf16 hi/lo split ----------------
__global__ __launch_bounds__(256) void split_bf16(
    const float* __restrict__ in, __nv_bfloat16* __restrict__ hi,
    __nv_bfloat16* __restrict__ lo, int n4)
{
    int i = blockIdx.x * 256 + threadIdx.x;
    if (i >= n4) return;
    float4 v = ((const float4*)in)[i];
    float f[4] = {v.x, v.y, v.z, v.w};
    union { __nv_bfloat16 b[4]; uint2 u; } H, L;
#pragma unroll
    for (int k = 0; k < 4; k++) {
        __nv_bfloat16 h = __float2bfloat16(f[k]);
        H.b[k] = h;
        L.b[k] = __float2bfloat16(f[k] - __bfloat162float(h));
    }
    ((uint2*)hi)[i] = H.u;
    ((uint2*)lo)[i] = L.u;
}

// ---------------- HMMA split-bf16 GEMM: BK=64, cp.async, ldmatrix ----------------
// C[m0+i, coff+n0+j] = sum_k A[i,k]*B[j,k]  (K-major, hi/lo bf16)
// 8 warps (2m x 4n), warp tile 64x32. smem: 2 stages x 4 tiles x [128 rows][72 halves].
#define BKC 64
#define NCHG (GK / BKC)          // 16
#define SROWG 72                 // halves per row (64 data + 8 pad -> 144B)
#define TILEG (128 * SROWG)      // halves per tile
#define STAGEG (4 * TILEG)
#define GEMM_SMEM (2 * STAGEG * 2)   // 147456 bytes

__global__ __launch_bounds__(256, 1) void hmma_gemm(
    const __nv_bfloat16* __restrict__ ah, const __nv_bfloat16* __restrict__ al,
    const __nv_bfloat16* __restrict__ bh, const __nv_bfloat16* __restrict__ bl,
    float* __restrict__ C, int ldc, int coff)
{
    extern __shared__ char smraw[];
    const uint32_t smb = smem_u32(smraw);

    const int tid = threadIdx.x;
    const int wid = tid >> 5;
    const int lid = tid & 31;
    const int wm = wid & 1;
    const int wn = wid >> 1;
    const int m0 = blockIdx.y * 128;
    const int n0 = blockIdx.x * 128;

    const __nv_bfloat16* gbase[4];
    gbase[0] = ah + (size_t)m0 * GK;
    gbase[1] = al + (size_t)m0 * GK;
    gbase[2] = bh + (size_t)n0 * GK;
    gbase[3] = bl + (size_t)n0 * GK;

    auto load_stage = [&](int kc, int stg) {
        const uint32_t base = smb + (uint32_t)stg * (STAGEG * 2);
#pragma unroll
        for (int i = 0; i < 4; i++) {
            int id = tid + 256 * i;
            int row = id >> 3, seg = id & 7;
            uint32_t soff = (uint32_t)(row * SROWG + seg * 8) * 2;
#pragma unroll
            for (int t = 0; t < 4; t++) {
                const __nv_bfloat16* src = gbase[t] + (size_t)row * GK + kc + seg * 8;
                cp16(base + (uint32_t)t * (TILEG * 2) + soff, src);
            }
        }
        cp_commit();
    };

    float acc[4][4][4];
#pragma unroll
    for (int i = 0; i < 4; i++)
#pragma unroll
        for (int j = 0; j < 4; j++)
#pragma unroll
            for (int k = 0; k < 4; k++) acc[i][j][k] = 0.f;

    const uint32_t frag_off =
        (uint32_t)((((lid & 7) + ((lid >> 3) & 1) * 8) * SROWG + (lid >> 4) * 8) * 2);

    load_stage(0, 0);
    load_stage(BKC, 1);

    for (int c = 0; c < NCHG; c++) {
        if (c + 2 < NCHG) cp_wait<1>(); else cp_wait<0>();
        __syncthreads();

        const uint32_t sbase = smb + (uint32_t)(c & 1) * (STAGEG * 2);

#pragma unroll
        for (int ks = 0; ks < 4; ks++) {
            uint32_t Ah[4][4], Al[4][4];
#pragma unroll
            for (int mf = 0; mf < 4; mf++) {
                uint32_t aaddr = sbase +
                    (uint32_t)(((wm * 64 + mf * 16) * SROWG + ks * 16) * 2) + frag_off;
                LDMX4(Ah[mf][0], Ah[mf][1], Ah[mf][2], Ah[mf][3], aaddr);
                LDMX4(Al[mf][0], Al[mf][1], Al[mf][2], Al[mf][3], aaddr + TILEG * 2);
            }
#pragma unroll
            for (int nfp = 0; nfp < 2; nfp++) {
                uint32_t baddr = sbase + 2u * (TILEG * 2) +
                    (uint32_t)(((wn * 32 + nfp * 16) * SROWG + ks * 16) * 2) + frag_off;
                uint32_t bh0, bh1, bh2, bh3, bl0, bl1, bl2, bl3;
                LDMX4(bh0, bh1, bh2, bh3, baddr);
                LDMX4(bl0, bl1, bl2, bl3, baddr + TILEG * 2);
                const int nf0 = 2 * nfp, nf1 = 2 * nfp + 1;
#pragma unroll
                for (int mf = 0; mf < 4; mf++) {
                    MMA_BF16(acc[mf][nf0][0], acc[mf][nf0][1], acc[mf][nf0][2], acc[mf][nf0][3],
                             Ah[mf][0], Ah[mf][1], Ah[mf][2], Ah[mf][3], bh0, bh2);
                    MMA_BF16(acc[mf][nf1][0], acc[mf][nf1][1], acc[mf][nf1][2], acc[mf][nf1][3],
                             Ah[mf][0], Ah[mf][1], Ah[mf][2], Ah[mf][3], bh1, bh3);
                    MMA_BF16(acc[mf][nf0][0], acc[mf][nf0][1], acc[mf][nf0][2], acc[mf][nf0][3],
                             Ah[mf][0], Ah[mf][1], Ah[mf][2], Ah[mf][3], bl0, bl2);
                    MMA_BF16(acc[mf][nf1][0], acc[mf][nf1][1], acc[mf][nf1][2], acc[mf][nf1][3],
                             Ah[mf][0], Ah[mf][1], Ah[mf][2], Ah[mf][3], bl1, bl3);
                    MMA_BF16(acc[mf][nf0][0], acc[mf][nf0][1], acc[mf][nf0][2], acc[mf][nf0][3],
                             Al[mf][0], Al[mf][1], Al[mf][2], Al[mf][3], bh0, bh2);
                    MMA_BF16(acc[mf][nf1][0], acc[mf][nf1][1], acc[mf][nf1][2], acc[mf][nf1][3],
                             Al[mf][0], Al[mf][1], Al[mf][2], Al[mf][3], bh1, bh3);
                }
            }
        }

        __syncthreads();
        if (c + 2 < NCHG) load_stage((c + 2) * BKC, c & 1);
    }

    const int r2 = lid >> 2;
    const int c2 = (lid & 3) * 2;
#pragma unroll
    for (int mf = 0; mf < 4; mf++) {
        const int row = m0 + wm * 64 + mf * 16 + r2;
#pragma unroll
        for (int nf = 0; nf < 4; nf++) {
            float* cp0 = C + (size_t)row * ldc + coff + n0 + wn * 32 + nf * 8 + c2;
            *(float2*)cp0 = make_float2(acc[mf][nf][0], acc[mf][nf][1]);
            *(float2*)(cp0 + 8 * (size_t)ldc) = make_float2(acc[mf][nf][2], acc[mf][nf][3]);
        }
    }
}

// ---------------- RMSNorm q -> per-head bf16 hi/lo (scale folded) ----------------
__global__ __launch_bounds__(256) void rms_q(const float* __restrict__ w)
{
    const int t = blockIdx.x;
    const int b = t >> 11, s = t & (SS - 1);
    const float* row = g_xqkv + (size_t)t * QKVW;
    const int tid = threadIdx.x;

    float v[4];
    float ss = 0.f;
#pragma unroll
    for (int i = 0; i < 4; i++) {
        v[i] = row[tid + 256 * i];
        ss = fmaf(v[i], v[i], ss);
    }
#pragma unroll
    for (int o = 16; o > 0; o >>= 1) ss += __shfl_xor_sync(0xffffffffu, ss, o);

    __shared__ float red[8];
    __shared__ float sscl;
    if ((tid & 31) == 0) red[tid >> 5] = ss;
    __syncthreads();
    if (tid == 0) {
        float tot = 0.f;
#pragma unroll
        for (int i = 0; i < 8; i++) tot += red[i];
        sscl = rsqrtf(tot * (1.f / 1024.f) + 1e-6f);
    }
    __syncthreads();
    float scl = sscl * 0.125f;   // fold 1/sqrt(64)
#pragma unroll
    for (int i = 0; i < 4; i++) {
        int idx = tid + 256 * i;
        float val = v[i] * scl * w[idx];
        int head = idx >> 6, d = idx & 63;
        size_t off = ((size_t)(b * NH + head) * SS + s) * 64 + d;
        __nv_bfloat16 h = __float2bfloat16(val);
        g_qh[off] = h;
        g_ql[off] = __float2bfloat16(val - __bfloat162float(h));
    }
}

// ---------------- K rmsnorm + V split -> per-kvhead bf16 hi/lo ----------------
__global__ __launch_bounds__(256) void prep_kv(const float* __restrict__ kw)
{
    const int t = blockIdx.x;
    const int b = t >> 11, s = t & (SS - 1);
    const float* row = g_xqkv + (size_t)t * QKVW;
    const int tid = threadIdx.x;
    const int kv = tid >> 6, d = tid & 63;
    const size_t off = ((size_t)(b * NKV + kv) * SS + s) * 64 + d;

    float kvl = row[1024 + tid];
    float ss = kvl * kvl;
#pragma unroll
    for (int o = 16; o > 0; o >>= 1) ss += __shfl_xor_sync(0xffffffffu, ss, o);

    __shared__ float red[8];
    __shared__ float sscl;
    if ((tid & 31) == 0) red[tid >> 5] = ss;
    __syncthreads();
    if (tid == 0) {
        float tot = 0.f;
#pragma unroll
        for (int i = 0; i < 8; i++) tot += red[i];
        sscl = rsqrtf(tot * (1.f / 256.f) + 1e-6f);
    }
    __syncthreads();

    float kn = kvl * sscl * kw[tid];
    __nv_bfloat16 kh = __float2bfloat16(kn);
    g_kh[off] = kh;
    g_kl[off] = __float2bfloat16(kn - __bfloat162float(kh));

    float vv = row[1280 + tid];
    __nv_bfloat16 vh = __float2bfloat16(vv);
    g_vh[off] = vh;
    g_vl[off] = __float2bfloat16(vv - __bfloat162float(vh));
}

// ---------------- tensor-core attention ----------------
// grid (S/128, NH, B), 256 threads = 8 warps, warp = 16 query rows.
// smem: 2 stages x 4 tiles (Kh,Kl,Vh,Vl), tile = 64 keys x 72 halves (144B rows).
#define TILEB 9216                    // 64*144
#define ATT_SMEM (2 * 4 * TILEB)      // 73728

__global__ __launch_bounds__(256, 2) void attn_tc()
{
    extern __shared__ char asm_[];
    const uint32_t smb = smem_u32(asm_);

    const int tid = threadIdx.x;
    const int wid = tid >> 5;
    const int lid = tid & 31;
    const int qstart = blockIdx.x * 128;
    const int head = blockIdx.y;
    const int b = blockIdx.z;
    const int kvh = head >> 2;

    const int r = lid >> 2;
    const int c2 = (lid & 3) * 2;
    const int qpos0 = qstart + wid * 16 + r;
    const float slope = exp2f(-0.5f * (float)(head + 1));

    const __nv_bfloat16* qbh = g_qh + ((size_t)(b * NH + head) * SS + qstart + wid * 16) * 64;
    const __nv_bfloat16* qbl = g_ql + ((size_t)(b * NH + head) * SS + qstart + wid * 16) * 64;
    uint32_t Qh[4][4];
#pragma unroll
    for (int ks = 0; ks < 4; ks++) {
        Qh[ks][0] = *(const uint32_t*)(qbh + r * 64 + ks * 16 + c2);
        Qh[ks][1] = *(const uint32_t*)(qbh + (r + 8) * 64 + ks * 16 + c2);
        Qh[ks][2] = *(const uint32_t*)(qbh + r * 64 + ks * 16 + 8 + c2);
        Qh[ks][3] = *(const uint32_t*)(qbh + (r + 8) * 64 + ks * 16 + 8 + c2);
    }

    float O[8][4];
#pragma unroll
    for (int i = 0; i < 8; i++)
#pragma unroll
        for (int j = 0; j < 4; j++) O[i][j] = 0.f;
    float m0 = -INFINITY, m1 = -INFINITY, l0 = 0.f, l1 = 0.f;

    const int kc0 = (qstart >= WIN) ? qstart - WIN : 0;
    const int nch = (qstart + 128 - kc0) >> 6;

    const int key_ld = tid >> 2;
    const int seg = tid & 3;
    const __nv_bfloat16* src_base[4];
    {
        size_t kvb = ((size_t)(b * NKV + kvh) * SS) * 64;
        src_base[0] = g_kh + kvb; src_base[1] = g_kl + kvb;
        src_base[2] = g_vh + kvb; src_base[3] = g_vl + kvb;
    }
    auto load_chunk = [&](int kc, int stg) {
        uint32_t sb = smb + stg * 4 * TILEB + key_ld * 144 + seg * 16;
#pragma unroll
        for (int t = 0; t < 4; t++) {
            const __nv_bfloat16* src = src_base[t] + (size_t)(kc + key_ld) * 64 + seg * 8;
            cp16(sb + t * TILEB, src);
            cp16(sb + t * TILEB + 64, src + 32);
        }
        cp_commit();
    };

    load_chunk(kc0, 0);
    if (nch > 1) load_chunk(kc0 + 64, 1);

    const uint32_t lane_off = (uint32_t)(((lid >> 4) * 8 + (lid & 7)) * 144 + ((lid >> 3) & 1) * 16);

    for (int c = 0; c < nch; c++) {
        if (c < nch - 1) cp_wait<1>(); else cp_wait<0>();
        __syncthreads();

        const uint32_t sb = smb + (c & 1) * 4 * TILEB;
        const int kc = kc0 + c * 64;

        // ---- scores: S = Qh*Kh + Qh*Kl + Ql*Kh ----
        float S[8][4];
#pragma unroll
        for (int i = 0; i < 8; i++)
#pragma unroll
            for (int j = 0; j < 4; j++) S[i][j] = 0.f;

#pragma unroll
        for (int ks = 0; ks < 4; ks++) {
            uint32_t Qlr[4];
            Qlr[0] = *(const uint32_t*)(qbl + r * 64 + ks * 16 + c2);
            Qlr[1] = *(const uint32_t*)(qbl + (r + 8) * 64 + ks * 16 + c2);
            Qlr[2] = *(const uint32_t*)(qbl + r * 64 + ks * 16 + 8 + c2);
            Qlr[3] = *(const uint32_t*)(qbl + (r + 8) * 64 + ks * 16 + 8 + c2);
#pragma unroll
            for (int nfp = 0; nfp < 4; nfp++) {
                uint32_t kh0, kh1, kh2, kh3, kl0, kl1, kl2, kl3;
                LDMX4(kh0, kh1, kh2, kh3, sb + nfp * 2304 + ks * 32 + lane_off);
                LDMX4(kl0, kl1, kl2, kl3, sb + TILEB + nfp * 2304 + ks * 32 + lane_off);
                MMA_BF16(S[2*nfp][0], S[2*nfp][1], S[2*nfp][2], S[2*nfp][3],
                         Qh[ks][0], Qh[ks][1], Qh[ks][2], Qh[ks][3], kh0, kh1);
                MMA_BF16(S[2*nfp+1][0], S[2*nfp+1][1], S[2*nfp+1][2], S[2*nfp+1][3],
                         Qh[ks][0], Qh[ks][1], Qh[ks][2], Qh[ks][3], kh2, kh3);
                MMA_BF16(S[2*nfp][0], S[2*nfp][1], S[2*nfp][2], S[2*nfp][3],
                         Qh[ks][0], Qh[ks][1], Qh[ks][2], Qh[ks][3], kl0, kl1);
                MMA_BF16(S[2*nfp+1][0], S[2*nfp+1][1], S[2*nfp+1][2], S[2*nfp+1][3],
                         Qh[ks][0], Qh[ks][1], Qh[ks][2], Qh[ks][3], kl2, kl3);
                MMA_BF16(S[2*nfp][0], S[2*nfp][1], S[2*nfp][2], S[2*nfp][3],
                         Qlr[0], Qlr[1], Qlr[2], Qlr[3], kh0, kh1);
                MMA_BF16(S[2*nfp+1][0], S[2*nfp+1][1], S[2*nfp+1][2], S[2*nfp+1][3],
                         Qlr[0], Qlr[1], Qlr[2], Qlr[3], kh2, kh3);
            }
        }

        // ---- bias + mask ----
#pragma unroll
        for (int nf = 0; nf < 8; nf++) {
            int rel0 = kc + nf * 8 + c2 - qpos0;
            int rel2 = rel0 - 8;
            S[nf][0] = (rel0     <= 0 && rel0     >= -WIN) ? fmaf(slope, (float)rel0,     S[nf][0]) : -INFINITY;
            S[nf][1] = (rel0 + 1 <= 0 && rel0 + 1 >= -WIN) ? fmaf(slope, (float)(rel0+1), S[nf][1]) : -INFINITY;
            S[nf][2] = (rel2     <= 0 && rel2     >= -WIN) ? fmaf(slope, (float)rel2,     S[nf][2]) : -INFINITY;
            S[nf][3] = (rel2 + 1 <= 0 && rel2 + 1 >= -WIN) ? fmaf(slope, (float)(rel2+1), S[nf][3]) : -INFINITY;
        }

        // ---- online softmax ----
        float mx0 = -INFINITY, mx1 = -INFINITY;
#pragma unroll
        for (int nf = 0; nf < 8; nf++) {
            mx0 = fmaxf(mx0, fmaxf(S[nf][0], S[nf][1]));
            mx1 = fmaxf(mx1, fmaxf(S[nf][2], S[nf][3]));
        }
        mx0 = fmaxf(mx0, __shfl_xor_sync(0xffffffffu, mx0, 1));
        mx0 = fmaxf(mx0, __shfl_xor_sync(0xffffffffu, mx0, 2));
        mx1 = fmaxf(mx1, __shfl_xor_sync(0xffffffffu, mx1, 1));
        mx1 = fmaxf(mx1, __shfl_xor_sync(0xffffffffu, mx1, 2));

        float mn0 = fmaxf(fmaxf(m0, mx0), -1e30f);
        float mn1 = fmaxf(fmaxf(m1, mx1), -1e30f);
        float a0 = __expf(m0 - mn0);
        float a1 = __expf(m1 - mn1);
        m0 = mn0; m1 = mn1;
        l0 *= a0; l1 *= a1;
#pragma unroll
        for (int nf = 0; nf < 8; nf++) {
            O[nf][0] *= a0; O[nf][1] *= a0;
            O[nf][2] *= a1; O[nf][3] *= a1;
        }
#pragma unroll
        for (int nf = 0; nf < 8; nf++) {
            S[nf][0] = __expf(S[nf][0] - m0);
            S[nf][1] = __expf(S[nf][1] - m0);
            S[nf][2] = __expf(S[nf][2] - m1);
            S[nf][3] = __expf(S[nf][3] - m1);
            l0 += S[nf][0] + S[nf][1];
            l1 += S[nf][2] + S[nf][3];
        }

        // ---- PV: O += (Ph+Pl)*(Vh+Vl), dropping Pl*Vl ----
#pragma unroll
        for (int ks = 0; ks < 4; ks++) {
            float x00 = S[2*ks][0],   x01 = S[2*ks][1],   x02 = S[2*ks][2],   x03 = S[2*ks][3];
            float x10 = S[2*ks+1][0], x11 = S[2*ks+1][1], x12 = S[2*ks+1][2], x13 = S[2*ks+1][3];
            float h00 = __bfloat162float(__float2bfloat16(x00));
            float h01 = __bfloat162float(__float2bfloat16(x01));
            float h02 = __bfloat162float(__float2bfloat16(x02));
            float h03 = __bfloat162float(__float2bfloat16(x03));
            float h10 = __bfloat162float(__float2bfloat16(x10));
            float h11 = __bfloat162float(__float2bfloat16(x11));
            float h12 = __bfloat162float(__float2bfloat16(x12));
            float h13 = __bfloat162float(__float2bfloat16(x13));
            uint32_t ph0 = packbf(x00, x01), ph1 = packbf(x02, x03);
            uint32_t ph2 = packbf(x10, x11), ph3 = packbf(x12, x13);
            uint32_t pl0 = packbf(x00 - h00, x01 - h01), pl1 = packbf(x02 - h02, x03 - h03);
            uint32_t pl2 = packbf(x10 - h10, x11 - h11), pl3 = packbf(x12 - h12, x13 - h13);
#pragma unroll
            for (int nfp = 0; nfp < 4; nfp++) {
                uint32_t v0, v1, v2, v3, w0, w1, w2, w3;
                LDMX4T(v0, v1, v2, v3, sb + 2 * TILEB + ks * 2304 + nfp * 32 + lane_off);
                LDMX4T(w0, w1, w2, w3, sb + 3 * TILEB + ks * 2304 + nfp * 32 + lane_off);
                MMA_BF16(O[2*nfp][0], O[2*nfp][1], O[2*nfp][2], O[2*nfp][3],
                         ph0, ph1, ph2, ph3, v0, v2);
                MMA_BF16(O[2*nfp+1][0], O[2*nfp+1][1], O[2*nfp+1][2], O[2*nfp+1][3],
                         ph0, ph1, ph2, ph3, v1, v3);
                MMA_BF16(O[2*nfp][0], O[2*nfp][1], O[2*nfp][2], O[2*nfp][3],
                         ph0, ph1, ph2, ph3, w0, w2);
                MMA_BF16(O[2*nfp+1][0], O[2*nfp+1][1], O[2*nfp+1][2], O[2*nfp+1][3],
                         ph0, ph1, ph2, ph3, w1, w3);
                MMA_BF16(O[2*nfp][0], O[2*nfp][1], O[2*nfp][2], O[2*nfp][3],
                         pl0, pl1, pl2, pl3, v0, v2);
                MMA_BF16(O[2*nfp+1][0], O[2*nfp+1][1], O[2*nfp+1][2], O[2*nfp+1][3],
                         pl0, pl1, pl2, pl3, v1, v3);
            }
        }

        __syncthreads();
        if (c + 2 < nch) load_chunk(kc0 + (c + 2) * 64, c & 1);
    }

    // ---- epilogue ----
    l0 += __shfl_xor_sync(0xffffffffu, l0, 1);
    l0 += __shfl_xor_sync(0xffffffffu, l0, 2);
    l1 += __shfl_xor_sync(0xffffffffu, l1, 1);
    l1 += __shfl_xor_sync(0xffffffffu, l1, 2);
    float inv0 = 1.f / l0, inv1 = 1.f / l1;

    size_t out0 = ((size_t)(b * SS + qpos0) * DIM) + head * 64;
    size_t out1 = out0 + (size_t)8 * DIM;
#pragma unroll
    for (int nf = 0; nf < 8; nf++) {
        float y0 = O[nf][0] * inv0, y1 = O[nf][1] * inv0;
        float y2 = O[nf][2] * inv1, y3 = O[nf][3] * inv1;
        int col = nf * 8 + c2;
        float h0 = __bfloat162float(__float2bfloat16(y0));
        float h1 = __bfloat162float(__float2bfloat16(y1));
        float h2 = __bfloat162float(__float2bfloat16(y2));
        float h3 = __bfloat162float(__float2bfloat16(y3));
        *(uint32_t*)(g_ah + out0 + col) = packbf(y0, y1);
        *(uint32_t*)(g_al + out0 + col) = packbf(y0 - h0, y1 - h1);
        *(uint32_t*)(g_ah + out1 + col) = packbf(y2, y3);
        *(uint32_t*)(g_al + out1 + col) = packbf(y2 - h2, y3 - h3);
    }
}

// ---------------- launch ----------------
extern "C" void kernel_launch(void* const* d_in, const int* in_sizes, int n_in,
                              void* d_out, int out_size)
{
    const float* x  = (const float*)d_in[0];
    const float* wq = (const float*)d_in[1];
    const float* wk = (const float*)d_in[2];
    const float* wv = (const float*)d_in[3];
    const float* wo = (const float*)d_in[4];
    const float* qw = (const float*)d_in[5];
    const float* kw = (const float*)d_in[6];
    float* out = (float*)d_out;

    float* xqkv = nullptr;
    __nv_bfloat16 *ah = nullptr, *al = nullptr, *wh = nullptr, *wl = nullptr;
    cudaGetSymbolAddress((void**)&xqkv, g_xqkv);
    cudaGetSymbolAddress((void**)&ah, g_ah);
    cudaGetSymbolAddress((void**)&al, g_al);
    cudaGetSymbolAddress((void**)&wh, g_wh);
    cudaGetSymbolAddress((void**)&wl, g_wl);

    static bool attr_done = false;
    if (!attr_done) {
        cudaFuncSetAttribute(hmma_gemm, cudaFuncAttributeMaxDynamicSharedMemorySize, GEMM_SMEM);
        cudaFuncSetAttribute(attn_tc, cudaFuncAttributeMaxDynamicSharedMemorySize, ATT_SMEM);
        attr_done = true;
    }

    split_bf16<<<(TT * DIM / 4) / 256, 256>>>(x, ah, al, TT * DIM / 4);
    split_bf16<<<(1024 * 1024 / 4) / 256, 256>>>(wq, wh + WQ_ROW * DIM, wl + WQ_ROW * DIM, 1024 * 1024 / 4);
    split_bf16<<<(256 * 1024 / 4) / 256, 256>>>(wk, wh + WK_ROW * DIM, wl + WK_ROW * DIM, 256 * 1024 / 4);
    split_bf16<<<(256 * 1024 / 4) / 256, 256>>>(wv, wh + WV_ROW * DIM, wl + WV_ROW * DIM, 256 * 1024 / 4);
    split_bf16<<<(1024 * 1024 / 4) / 256, 256>>>(wo, wh + WO_ROW * DIM, wl + WO_ROW * DIM, 1024 * 1024 / 4);

    // merged QKV projection
    hmma_gemm<<<dim3(QKVW / 128, TT / 128), 256, GEMM_SMEM>>>(ah, al, wh, wl, xqkv, QKVW, 0);

    rms_q<<<TT, 256>>>(qw);
    prep_kv<<<TT, 256>>>(kw);

    attn_tc<<<dim3(SS / 128, NH, BB), 256, ATT_SMEM>>>();

    // output projection (attention wrote g_ah/g_al directly)
    hmma_gemm<<<dim3(DIM / 128, TT / 128), 256, GEMM_SMEM>>>(
        ah, al, wh + (size_t)WO_ROW * DIM, wl + (size_t)WO_ROW * DIM, out, DIM, 0);
}

// round 6
// speedup vs baseline: 3.1104x; 1.0625x over previous
#include <cuda_runtime.h>
#include <cuda_bf16.h>
#include <math.h>
#include <stdint.h>

#define DIM   1024
#define NH    16
#define NKV   4
#define HD    64
#define WIN   512
#define BB    2
#define SS    2048
#define TT    (BB*SS)
#define QKVW  1536   // 1024 q | 256 k | 256 v per token
#define GK    1024   // K dim of every GEMM
#define LOG2E 1.4426950408889634f

// ---------------- scratch (no allocs allowed) ----------------
__device__ float g_xqkv[(size_t)TT * QKVW];          // fp32 qkv projections
__device__ __nv_bfloat16 g_ah[(size_t)TT * DIM];     // activation hi (x, then attn out)
__device__ __nv_bfloat16 g_al[(size_t)TT * DIM];     // activation lo
__device__ __nv_bfloat16 g_wh[(size_t)2560 * DIM];   // weights hi: wq|wk|wv|wo
__device__ __nv_bfloat16 g_wl[(size_t)2560 * DIM];
__device__ __nv_bfloat16 g_qh[(size_t)TT * DIM];     // per-head Q hi  [(b*NH+h)*SS+s][64]
__device__ __nv_bfloat16 g_ql[(size_t)TT * DIM];
__device__ __nv_bfloat16 g_kh[(size_t)TT * 256];     // per-kvhead K hi [(b*NKV+kv)*SS+s][64]
__device__ __nv_bfloat16 g_kl[(size_t)TT * 256];
__device__ __nv_bfloat16 g_vh[(size_t)TT * 256];
__device__ __nv_bfloat16 g_vl[(size_t)TT * 256];
#define WO_ROW 1536

// ---------------- small PTX helpers ----------------
__device__ __forceinline__ uint32_t smem_u32(const void* p) {
    uint32_t a;
    asm("{ .reg .u64 t; cvta.to.shared.u64 t, %1; cvt.u32.u64 %0, t; }" : "=r"(a) : "l"(p));
    return a;
}
__device__ __forceinline__ void cp16(uint32_t s, const void* g) {
    asm volatile("{ .reg .u64 gg; cvta.to.global.u64 gg, %1; cp.async.cg.shared.global [%0], [gg], 16; }"
                 :: "r"(s), "l"(g) : "memory");
}
__device__ __forceinline__ void cp_commit() { asm volatile("cp.async.commit_group;" ::: "memory"); }
template <int N>
__device__ __forceinline__ void cp_wait() { asm volatile("cp.async.wait_group %0;" :: "n"(N) : "memory"); }

__device__ __forceinline__ uint32_t packbf(float lo, float hi) {
    uint32_t r;
    asm("cvt.rn.bf16x2.f32 %0, %1, %2;" : "=r"(r) : "f"(hi), "f"(lo));
    return r;
}

#define MMA_BF16(c0,c1,c2,c3, a0,a1,a2,a3, b0,b1) \
    asm volatile("mma.sync.aligned.m16n8k16.row.col.f32.bf16.bf16.f32 " \
                 "{%0,%1,%2,%3}, {%4,%5,%6,%7}, {%8,%9}, {%0,%1,%2,%3};" \
                 : "+f"(c0), "+f"(c1), "+f"(c2), "+f"(c3) \
                 : "r"(a0), "r"(a1), "r"(a2), "r"(a3), "r"(b0), "r"(b1))

#define LDMX4(r0,r1,r2,r3, addr) \
    asm volatile("ldmatrix.sync.aligned.m8n8.x4.shared.b16 {%0,%1,%2,%3}, [%4];" \
                 : "=r"(r0), "=r"(r1), "=r"(r2), "=r"(r3) : "r"(addr))
#define LDMX4T(r0,r1,r2,r3, addr) \
    asm volatile("ldmatrix.sync.aligned.m8n8.x4.trans.shared.b16 {%0,%1,%2,%3}, [%4];" \
                 : "=r"(r0), "=r"(r1), "=r"(r2), "=r"(r3) : "r"(addr))

// ---------------- fp32 -> bf16 hi/lo split (x) ----------------
__global__ __launch_bounds__(256) void split_bf16(
    const float* __restrict__ in, __nv_bfloat16* __restrict__ hi,
    __nv_bfloat16* __restrict__ lo, int n4)
{
    int i = blockIdx.x * 256 + threadIdx.x;
    if (i >= n4) return;
    float4 v = ((const float4*)in)[i];
    float f[4] = {v.x, v.y, v.z, v.w};
    union { __nv_bfloat16 b[4]; uint2 u; } H, L;
#pragma unroll
    for (int k = 0; k < 4; k++) {
        __nv_bfloat16 h = __float2bfloat16(f[k]);
        H.b[k] = h;
        L.b[k] = __float2bfloat16(f[k] - __bfloat162float(h));
    }
    ((uint2*)hi)[i] = H.u;
    ((uint2*)lo)[i] = L.u;
}

// ---------------- all weights -> stacked bf16 hi/lo, one kernel ----------------
__global__ __launch_bounds__(256) void wsplit_all(
    const float* __restrict__ wq, const float* __restrict__ wk,
    const float* __restrict__ wv, const float* __restrict__ wo)
{
    int i = blockIdx.x * 256 + threadIdx.x;   // float4 index, 0..655359
    const float* src;
    int local;
    if (i < 262144)      { src = wq; local = i; }
    else if (i < 327680) { src = wk; local = i - 262144; }
    else if (i < 393216) { src = wv; local = i - 327680; }
    else                 { src = wo; local = i - 393216; }
    float4 v = ((const float4*)src)[local];
    float f[4] = {v.x, v.y, v.z, v.w};
    union { __nv_bfloat16 b[4]; uint2 u; } H, L;
#pragma unroll
    for (int k = 0; k < 4; k++) {
        __nv_bfloat16 h = __float2bfloat16(f[k]);
        H.b[k] = h;
        L.b[k] = __float2bfloat16(f[k] - __bfloat162float(h));
    }
    ((uint2*)g_wh)[i] = H.u;
    ((uint2*)g_wl)[i] = L.u;
}

// ---------------- HMMA split-bf16 GEMM: BK=64, 3-stage cp.async, ldmatrix ----------------
#define BKC 64
#define NCHG (GK / BKC)          // 16
#define SROWG 72                 // halves per row (64 data + 8 pad -> 144B)
#define TILEG (128 * SROWG)      // halves per tile
#define STAGEG (4 * TILEG)
#define GEMM_SMEM (3 * STAGEG * 2)   // 221184 bytes

__global__ __launch_bounds__(256, 1) void hmma_gemm(
    const __nv_bfloat16* __restrict__ ah, const __nv_bfloat16* __restrict__ al,
    const __nv_bfloat16* __restrict__ bh, const __nv_bfloat16* __restrict__ bl,
    float* __restrict__ C, int ldc, int coff)
{
    extern __shared__ char smraw[];
    const uint32_t smb = smem_u32(smraw);

    const int tid = threadIdx.x;
    const int wid = tid >> 5;
    const int lid = tid & 31;
    const int wm = wid & 1;
    const int wn = wid >> 1;
    const int m0 = blockIdx.y * 128;
    const int n0 = blockIdx.x * 128;

    const __nv_bfloat16* gbase[4];
    gbase[0] = ah + (size_t)m0 * GK;
    gbase[1] = al + (size_t)m0 * GK;
    gbase[2] = bh + (size_t)n0 * GK;
    gbase[3] = bl + (size_t)n0 * GK;

    auto load_stage = [&](int kc, int stg) {
        const uint32_t base = smb + (uint32_t)stg * (STAGEG * 2);
#pragma unroll
        for (int i = 0; i < 4; i++) {
            int id = tid + 256 * i;
            int row = id >> 3, seg = id & 7;
            uint32_t soff = (uint32_t)(row * SROWG + seg * 8) * 2;
#pragma unroll
            for (int t = 0; t < 4; t++) {
                const __nv_bfloat16* src = gbase[t] + (size_t)row * GK + kc + seg * 8;
                cp16(base + (uint32_t)t * (TILEG * 2) + soff, src);
            }
        }
        cp_commit();
    };

    float acc[4][4][4];
#pragma unroll
    for (int i = 0; i < 4; i++)
#pragma unroll
        for (int j = 0; j < 4; j++)
#pragma unroll
            for (int k = 0; k < 4; k++) acc[i][j][k] = 0.f;

    const uint32_t frag_off =
        (uint32_t)((((lid & 7) + ((lid >> 3) & 1) * 8) * SROWG + (lid >> 4) * 8) * 2);

    load_stage(0, 0);
    load_stage(BKC, 1);
    load_stage(2 * BKC, 2);

    for (int c = 0; c < NCHG; c++) {
        if (c <= NCHG - 3)      cp_wait<2>();
        else if (c == NCHG - 2) cp_wait<1>();
        else                    cp_wait<0>();
        __syncthreads();

        const uint32_t sbase = smb + (uint32_t)(c % 3) * (STAGEG * 2);

#pragma unroll
        for (int ks = 0; ks < 4; ks++) {
            uint32_t Ah[4][4], Al[4][4];
#pragma unroll
            for (int mf = 0; mf < 4; mf++) {
                uint32_t aaddr = sbase +
                    (uint32_t)(((wm * 64 + mf * 16) * SROWG + ks * 16) * 2) + frag_off;
                LDMX4(Ah[mf][0], Ah[mf][1], Ah[mf][2], Ah[mf][3], aaddr);
                LDMX4(Al[mf][0], Al[mf][1], Al[mf][2], Al[mf][3], aaddr + TILEG * 2);
            }
#pragma unroll
            for (int nfp = 0; nfp < 2; nfp++) {
                uint32_t baddr = sbase + 2u * (TILEG * 2) +
                    (uint32_t)(((wn * 32 + nfp * 16) * SROWG + ks * 16) * 2) + frag_off;
                uint32_t bh0, bh1, bh2, bh3, bl0, bl1, bl2, bl3;
                LDMX4(bh0, bh1, bh2, bh3, baddr);
                LDMX4(bl0, bl1, bl2, bl3, baddr + TILEG * 2);
                const int nf0 = 2 * nfp, nf1 = 2 * nfp + 1;
#pragma unroll
                for (int mf = 0; mf < 4; mf++) {
                    MMA_BF16(acc[mf][nf0][0], acc[mf][nf0][1], acc[mf][nf0][2], acc[mf][nf0][3],
                             Ah[mf][0], Ah[mf][1], Ah[mf][2], Ah[mf][3], bh0, bh2);
                    MMA_BF16(acc[mf][nf1][0], acc[mf][nf1][1], acc[mf][nf1][2], acc[mf][nf1][3],
                             Ah[mf][0], Ah[mf][1], Ah[mf][2], Ah[mf][3], bh1, bh3);
                    MMA_BF16(acc[mf][nf0][0], acc[mf][nf0][1], acc[mf][nf0][2], acc[mf][nf0][3],
                             Ah[mf][0], Ah[mf][1], Ah[mf][2], Ah[mf][3], bl0, bl2);
                    MMA_BF16(acc[mf][nf1][0], acc[mf][nf1][1], acc[mf][nf1][2], acc[mf][nf1][3],
                             Ah[mf][0], Ah[mf][1], Ah[mf][2], Ah[mf][3], bl1, bl3);
                    MMA_BF16(acc[mf][nf0][0], acc[mf][nf0][1], acc[mf][nf0][2], acc[mf][nf0][3],
                             Al[mf][0], Al[mf][1], Al[mf][2], Al[mf][3], bh0, bh2);
                    MMA_BF16(acc[mf][nf1][0], acc[mf][nf1][1], acc[mf][nf1][2], acc[mf][nf1][3],
                             Al[mf][0], Al[mf][1], Al[mf][2], Al[mf][3], bh1, bh3);
                }
            }
        }

        __syncthreads();
        if (c + 3 < NCHG) load_stage((c + 3) * BKC, c % 3);
    }

    const int r2 = lid >> 2;
    const int c2 = (lid & 3) * 2;
#pragma unroll
    for (int mf = 0; mf < 4; mf++) {
        const int row = m0 + wm * 64 + mf * 16 + r2;
#pragma unroll
        for (int nf = 0; nf < 4; nf++) {
            float* cp0 = C + (size_t)row * ldc + coff + n0 + wn * 32 + nf * 8 + c2;
            *(float2*)cp0 = make_float2(acc[mf][nf][0], acc[mf][nf][1]);
            *(float2*)(cp0 + 8 * (size_t)ldc) = make_float2(acc[mf][nf][2], acc[mf][nf][3]);
        }
    }
}

// ---------------- fused q-rms + k-rms + v split ----------------
// Q gets 0.125*LOG2E folded in (attention runs in log2 domain).
__global__ __launch_bounds__(256) void prep_qkv(
    const float* __restrict__ qw, const float* __restrict__ kw)
{
    const int t = blockIdx.x;
    const int b = t >> 11, s = t & (SS - 1);
    const float* row = g_xqkv + (size_t)t * QKVW;
    const int tid = threadIdx.x;

    float v[4];
    float ssq = 0.f;
#pragma unroll
    for (int i = 0; i < 4; i++) {
        v[i] = row[tid + 256 * i];
        ssq = fmaf(v[i], v[i], ssq);
    }
    float kvl = row[1024 + tid];
    float ssk = kvl * kvl;
    float vv = row[1280 + tid];

#pragma unroll
    for (int o = 16; o > 0; o >>= 1) {
        ssq += __shfl_xor_sync(0xffffffffu, ssq, o);
        ssk += __shfl_xor_sync(0xffffffffu, ssk, o);
    }

    __shared__ float redq[8], redk[8];
    __shared__ float sclq_s, sclk_s;
    if ((tid & 31) == 0) { redq[tid >> 5] = ssq; redk[tid >> 5] = ssk; }
    __syncthreads();
    if (tid == 0) {
        float tq = 0.f, tk = 0.f;
#pragma unroll
        for (int i = 0; i < 8; i++) { tq += redq[i]; tk += redk[i]; }
        sclq_s = rsqrtf(tq * (1.f / 1024.f) + 1e-6f) * (0.125f * LOG2E);
        sclk_s = rsqrtf(tk * (1.f / 256.f) + 1e-6f);
    }
    __syncthreads();
    const float sclq = sclq_s, sclk = sclk_s;

#pragma unroll
    for (int i = 0; i < 4; i++) {
        int idx = tid + 256 * i;
        float val = v[i] * sclq * qw[idx];
        int head = idx >> 6, d = idx & 63;
        size_t off = ((size_t)(b * NH + head) * SS + s) * 64 + d;
        __nv_bfloat16 h = __float2bfloat16(val);
        g_qh[off] = h;
        g_ql[off] = __float2bfloat16(val - __bfloat162float(h));
    }

    const int kv = tid >> 6, d = tid & 63;
    const size_t off = ((size_t)(b * NKV + kv) * SS + s) * 64 + d;
    float kn = kvl * sclk * kw[tid];
    __nv_bfloat16 kh = __float2bfloat16(kn);
    g_kh[off] = kh;
    g_kl[off] = __float2bfloat16(kn - __bfloat162float(kh));
    __nv_bfloat16 vh = __float2bfloat16(vv);
    g_vh[off] = vh;
    g_vl[off] = __float2bfloat16(vv - __bfloat162float(vh));
}

// ---------------- tensor-core attention (log2 domain) ----------------
#define TILEB 9216                    // 64*144
#define ATT_SMEM (2 * 4 * TILEB)      // 73728

__global__ __launch_bounds__(256, 2) void attn_tc()
{
    extern __shared__ char asm_[];
    const uint32_t smb = smem_u32(asm_);

    const int tid = threadIdx.x;
    const int wid = tid >> 5;
    const int lid = tid & 31;
    const int qstart = blockIdx.x * 128;
    const int head = blockIdx.y;
    const int b = blockIdx.z;
    const int kvh = head >> 2;

    const int r = lid >> 2;
    const int c2 = (lid & 3) * 2;
    const int qpos0 = qstart + wid * 16 + r;
    const int wqmin = qstart + wid * 16;        // warp's min query pos
    const int wqmax = wqmin + 15;               // warp's max query pos
    const float slope = exp2f(-0.5f * (float)(head + 1)) * LOG2E;

    const __nv_bfloat16* qbh = g_qh + ((size_t)(b * NH + head) * SS + qstart + wid * 16) * 64;
    const __nv_bfloat16* qbl = g_ql + ((size_t)(b * NH + head) * SS + qstart + wid * 16) * 64;
    uint32_t Qh[4][4];
#pragma unroll
    for (int ks = 0; ks < 4; ks++) {
        Qh[ks][0] = *(const uint32_t*)(qbh + r * 64 + ks * 16 + c2);
        Qh[ks][1] = *(const uint32_t*)(qbh + (r + 8) * 64 + ks * 16 + c2);
        Qh[ks][2] = *(const uint32_t*)(qbh + r * 64 + ks * 16 + 8 + c2);
        Qh[ks][3] = *(const uint32_t*)(qbh + (r + 8) * 64 + ks * 16 + 8 + c2);
    }

    float O[8][4];
#pragma unroll
    for (int i = 0; i < 8; i++)
#pragma unroll
        for (int j = 0; j < 4; j++) O[i][j] = 0.f;
    float m0 = -INFINITY, m1 = -INFINITY, l0 = 0.f, l1 = 0.f;

    const int kc0 = (qstart >= WIN) ? qstart - WIN : 0;
    const int nch = (qstart + 128 - kc0) >> 6;

    const int key_ld = tid >> 2;
    const int seg = tid & 3;
    const __nv_bfloat16* src_base[4];
    {
        size_t kvb = ((size_t)(b * NKV + kvh) * SS) * 64;
        src_base[0] = g_kh + kvb; src_base[1] = g_kl + kvb;
        src_base[2] = g_vh + kvb; src_base[3] = g_vl + kvb;
    }
    auto load_chunk = [&](int kc, int stg) {
        uint32_t sb = smb + stg * 4 * TILEB + key_ld * 144 + seg * 16;
#pragma unroll
        for (int t = 0; t < 4; t++) {
            const __nv_bfloat16* src = src_base[t] + (size_t)(kc + key_ld) * 64 + seg * 8;
            cp16(sb + t * TILEB, src);
            cp16(sb + t * TILEB + 64, src + 32);
        }
        cp_commit();
    };

    load_chunk(kc0, 0);
    if (nch > 1) load_chunk(kc0 + 64, 1);

    const uint32_t lane_off = (uint32_t)(((lid >> 4) * 8 + (lid & 7)) * 144 + ((lid >> 3) & 1) * 16);

    for (int c = 0; c < nch; c++) {
        if (c < nch - 1) cp_wait<1>(); else cp_wait<0>();
        __syncthreads();

        const uint32_t sb = smb + (c & 1) * 4 * TILEB;
        const int kc = kc0 + c * 64;

        // whole-chunk skip (uniform per warp): fully causal-masked or fully out-of-window
        const bool active = (kc <= wqmax) && (kc + 63 >= wqmin - WIN);
        if (active) {

        // ---- scores: S = Qh*Kh + Qh*Kl + Ql*Kh (log2 domain via folded scale) ----
        float S[8][4];
#pragma unroll
        for (int i = 0; i < 8; i++)
#pragma unroll
            for (int j = 0; j < 4; j++) S[i][j] = 0.f;

#pragma unroll
        for (int ks = 0; ks < 4; ks++) {
            uint32_t Qlr[4];
            Qlr[0] = *(const uint32_t*)(qbl + r * 64 + ks * 16 + c2);
            Qlr[1] = *(const uint32_t*)(qbl + (r + 8) * 64 + ks * 16 + c2);
            Qlr[2] = *(const uint32_t*)(qbl + r * 64 + ks * 16 + 8 + c2);
            Qlr[3] = *(const uint32_t*)(qbl + (r + 8) * 64 + ks * 16 + 8 + c2);
#pragma unroll
            for (int nfp = 0; nfp < 4; nfp++) {
                uint32_t kh0, kh1, kh2, kh3, kl0, kl1, kl2, kl3;
                LDMX4(kh0, kh1, kh2, kh3, sb + nfp * 2304 + ks * 32 + lane_off);
                LDMX4(kl0, kl1, kl2, kl3, sb + TILEB + nfp * 2304 + ks * 32 + lane_off);
                MMA_BF16(S[2*nfp][0], S[2*nfp][1], S[2*nfp][2], S[2*nfp][3],
                         Qh[ks][0], Qh[ks][1], Qh[ks][2], Qh[ks][3], kh0, kh1);
                MMA_BF16(S[2*nfp+1][0], S[2*nfp+1][1], S[2*nfp+1][2], S[2*nfp+1][3],
                         Qh[ks][0], Qh[ks][1], Qh[ks][2], Qh[ks][3], kh2, kh3);
                MMA_BF16(S[2*nfp][0], S[2*nfp][1], S[2*nfp][2], S[2*nfp][3],
                         Qh[ks][0], Qh[ks][1], Qh[ks][2], Qh[ks][3], kl0, kl1);
                MMA_BF16(S[2*nfp+1][0], S[2*nfp+1][1], S[2*nfp+1][2], S[2*nfp+1][3],
                         Qh[ks][0], Qh[ks][1], Qh[ks][2], Qh[ks][3], kl2, kl3);
                MMA_BF16(S[2*nfp][0], S[2*nfp][1], S[2*nfp][2], S[2*nfp][3],
                         Qlr[0], Qlr[1], Qlr[2], Qlr[3], kh0, kh1);
                MMA_BF16(S[2*nfp+1][0], S[2*nfp+1][1], S[2*nfp+1][2], S[2*nfp+1][3],
                         Qlr[0], Qlr[1], Qlr[2], Qlr[3], kh2, kh3);
            }
        }

        // ---- bias + mask (slope already has log2e) ----
#pragma unroll
        for (int nf = 0; nf < 8; nf++) {
            int rel0 = kc + nf * 8 + c2 - qpos0;
            int rel2 = rel0 - 8;
            S[nf][0] = (rel0     <= 0 && rel0     >= -WIN) ? fmaf(slope, (float)rel0,     S[nf][0]) : -INFINITY;
            S[nf][1] = (rel0 + 1 <= 0 && rel0 + 1 >= -WIN) ? fmaf(slope, (float)(rel0+1), S[nf][1]) : -INFINITY;
            S[nf][2] = (rel2     <= 0 && rel2     >= -WIN) ? fmaf(slope, (float)rel2,     S[nf][2]) : -INFINITY;
            S[nf][3] = (rel2 + 1 <= 0 && rel2 + 1 >= -WIN) ? fmaf(slope, (float)(rel2+1), S[nf][3]) : -INFINITY;
        }

        // ---- online softmax (exp2) ----
        float mx0 = -INFINITY, mx1 = -INFINITY;
#pragma unroll
        for (int nf = 0; nf < 8; nf++) {
            mx0 = fmaxf(mx0, fmaxf(S[nf][0], S[nf][1]));
            mx1 = fmaxf(mx1, fmaxf(S[nf][2], S[nf][3]));
        }
        mx0 = fmaxf(mx0, __shfl_xor_sync(0xffffffffu, mx0, 1));
        mx0 = fmaxf(mx0, __shfl_xor_sync(0xffffffffu, mx0, 2));
        mx1 = fmaxf(mx1, __shfl_xor_sync(0xffffffffu, mx1, 1));
        mx1 = fmaxf(mx1, __shfl_xor_sync(0xffffffffu, mx1, 2));

        float mn0 = fmaxf(fmaxf(m0, mx0), -1e30f);
        float mn1 = fmaxf(fmaxf(m1, mx1), -1e30f);
        float a0 = exp2f(m0 - mn0);
        float a1 = exp2f(m1 - mn1);
        m0 = mn0; m1 = mn1;
        l0 *= a0; l1 *= a1;
#pragma unroll
        for (int nf = 0; nf < 8; nf++) {
            O[nf][0] *= a0; O[nf][1] *= a0;
            O[nf][2] *= a1; O[nf][3] *= a1;
        }
#pragma unroll
        for (int nf = 0; nf < 8; nf++) {
            S[nf][0] = exp2f(S[nf][0] - m0);
            S[nf][1] = exp2f(S[nf][1] - m0);
            S[nf][2] = exp2f(S[nf][2] - m1);
            S[nf][3] = exp2f(S[nf][3] - m1);
            l0 += S[nf][0] + S[nf][1];
            l1 += S[nf][2] + S[nf][3];
        }

        // ---- PV: O += (Ph+Pl)*Vh + Ph*Vl ----
#pragma unroll
        for (int ks = 0; ks < 4; ks++) {
            float x00 = S[2*ks][0],   x01 = S[2*ks][1],   x02 = S[2*ks][2],   x03 = S[2*ks][3];
            float x10 = S[2*ks+1][0], x11 = S[2*ks+1][1], x12 = S[2*ks+1][2], x13 = S[2*ks+1][3];
            float h00 = __bfloat162float(__float2bfloat16(x00));
            float h01 = __bfloat162float(__float2bfloat16(x01));
            float h02 = __bfloat162float(__float2bfloat16(x02));
            float h03 = __bfloat162float(__float2bfloat16(x03));
            float h10 = __bfloat162float(__float2bfloat16(x10));
            float h11 = __bfloat162float(__float2bfloat16(x11));
            float h12 = __bfloat162float(__float2bfloat16(x12));
            float h13 = __bfloat162float(__float2bfloat16(x13));
            uint32_t ph0 = packbf(x00, x01), ph1 = packbf(x02, x03);
            uint32_t ph2 = packbf(x10, x11), ph3 = packbf(x12, x13);
            uint32_t pl0 = packbf(x00 - h00, x01 - h01), pl1 = packbf(x02 - h02, x03 - h03);
            uint32_t pl2 = packbf(x10 - h10, x11 - h11), pl3 = packbf(x12 - h12, x13 - h13);
#pragma unroll
            for (int nfp = 0; nfp < 4; nfp++) {
                uint32_t v0, v1, v2, v3, w0, w1, w2, w3;
                LDMX4T(v0, v1, v2, v3, sb + 2 * TILEB + ks * 2304 + nfp * 32 + lane_off);
                LDMX4T(w0, w1, w2, w3, sb + 3 * TILEB + ks * 2304 + nfp * 32 + lane_off);
                MMA_BF16(O[2*nfp][0], O[2*nfp][1], O[2*nfp][2], O[2*nfp][3],
                         ph0, ph1, ph2, ph3, v0, v2);
                MMA_BF16(O[2*nfp+1][0], O[2*nfp+1][1], O[2*nfp+1][2], O[2*nfp+1][3],
                         ph0, ph1, ph2, ph3, v1, v3);
                MMA_BF16(O[2*nfp][0], O[2*nfp][1], O[2*nfp][2], O[2*nfp][3],
                         ph0, ph1, ph2, ph3, w0, w2);
                MMA_BF16(O[2*nfp+1][0], O[2*nfp+1][1], O[2*nfp+1][2], O[2*nfp+1][3],
                         ph0, ph1, ph2, ph3, w1, w3);
                MMA_BF16(O[2*nfp][0], O[2*nfp][1], O[2*nfp][2], O[2*nfp][3],
                         pl0, pl1, pl2, pl3, v0, v2);
                MMA_BF16(O[2*nfp+1][0], O[2*nfp+1][1], O[2*nfp+1][2], O[2*nfp+1][3],
                         pl0, pl1, pl2, pl3, v1, v3);
            }
        }

        }  // active

        __syncthreads();
        if (c + 2 < nch) load_chunk(kc0 + (c + 2) * 64, c & 1);
    }

    // ---- epilogue ----
    l0 += __shfl_xor_sync(0xffffffffu, l0, 1);
    l0 += __shfl_xor_sync(0xffffffffu, l0, 2);
    l1 += __shfl_xor_sync(0xffffffffu, l1, 1);
    l1 += __shfl_xor_sync(0xffffffffu, l1, 2);
    float inv0 = 1.f / l0, inv1 = 1.f / l1;

    size_t out0 = ((size_t)(b * SS + qpos0) * DIM) + head * 64;
    size_t out1 = out0 + (size_t)8 * DIM;
#pragma unroll
    for (int nf = 0; nf < 8; nf++) {
        float y0 = O[nf][0] * inv0, y1 = O[nf][1] * inv0;
        float y2 = O[nf][2] * inv1, y3 = O[nf][3] * inv1;
        int col = nf * 8 + c2;
        float h0 = __bfloat162float(__float2bfloat16(y0));
        float h1 = __bfloat162float(__float2bfloat16(y1));
        float h2 = __bfloat162float(__float2bfloat16(y2));
        float h3 = __bfloat162float(__float2bfloat16(y3));
        *(uint32_t*)(g_ah + out0 + col) = packbf(y0, y1);
        *(uint32_t*)(g_al + out0 + col) = packbf(y0 - h0, y1 - h1);
        *(uint32_t*)(g_ah + out1 + col) = packbf(y2, y3);
        *(uint32_t*)(g_al + out1 + col) = packbf(y2 - h2, y3 - h3);
    }
}

// ---------------- launch ----------------
extern "C" void kernel_launch(void* const* d_in, const int* in_sizes, int n_in,
                              void* d_out, int out_size)
{
    const float* x  = (const float*)d_in[0];
    const float* wq = (const float*)d_in[1];
    const float* wk = (const float*)d_in[2];
    const float* wv = (const float*)d_in[3];
    const float* wo = (const float*)d_in[4];
    const float* qw = (const float*)d_in[5];
    const float* kw = (const float*)d_in[6];
    float* out = (float*)d_out;

    float* xqkv = nullptr;
    __nv_bfloat16 *ah = nullptr, *al = nullptr, *wh = nullptr, *wl = nullptr;
    cudaGetSymbolAddress((void**)&xqkv, g_xqkv);
    cudaGetSymbolAddress((void**)&ah, g_ah);
    cudaGetSymbolAddress((void**)&al, g_al);
    cudaGetSymbolAddress((void**)&wh, g_wh);
    cudaGetSymbolAddress((void**)&wl, g_wl);

    static bool attr_done = false;
    if (!attr_done) {
        cudaFuncSetAttribute(hmma_gemm, cudaFuncAttributeMaxDynamicSharedMemorySize, GEMM_SMEM);
        cudaFuncSetAttribute(attn_tc, cudaFuncAttributeMaxDynamicSharedMemorySize, ATT_SMEM);
        attr_done = true;
    }

    // 1. x hi/lo split
    split_bf16<<<(TT * DIM / 4) / 256, 256>>>(x, ah, al, TT * DIM / 4);
    // 2. all weights hi/lo split (one kernel)
    wsplit_all<<<2560, 256>>>(wq, wk, wv, wo);
    // 3. merged QKV projection  (profiled slot)
    hmma_gemm<<<dim3(QKVW / 128, TT / 128), 256, GEMM_SMEM>>>(ah, al, wh, wl, xqkv, QKVW, 0);
    // 4. fused rmsnorm q/k + v split
    prep_qkv<<<TT, 256>>>(qw, kw);
    // 5. attention
    attn_tc<<<dim3(SS / 128, NH, BB), 256, ATT_SMEM>>>();
    // 6. output projection
    hmma_gemm<<<dim3(DIM / 128, TT / 128), 256, GEMM_SMEM>>>(
        ah, al, wh + (size_t)WO_ROW * DIM, wl + (size_t)WO_ROW * DIM, out, DIM, 0);
}